// round 11
// baseline (speedup 1.0000x reference)
#include <cuda_runtime.h>
#include <cuda_bf16.h>
#include <cuda_fp16.h>
#include <math.h>
#include <stdint.h>

#define NI 10000
#define H  128
#define L  50
#define B  64
#define E  160000
#define NC 9999
#define NCP 10112     // NC padded to 128*79
#define LP 64         // L padded for MMA
#define NITEMS (79 * 8)   // n-tiles x batch-groups

// ---------------- persistent device scratch ----------------
__device__ float g_agg[NI * H];
__device__ int   g_mark[NI];
__device__ unsigned g_ticket;
__device__ float g_sg [B * L * H];        // pre-relu
__device__ float g_ao [B * L * 256];      // [ain|aout]
__device__ float g_cat[B * L * 384];      // [inp(256) | h0(128)]
__device__ float g_gates[B * L * 512];    // [r_sum | z_sum | i_n | h_n]
__device__ float g_final[B * L * H];
__device__ float g_kv [B * L * 2 * H];
__device__ float g_last[B * H];
__device__ float g_u  [B * H];
__device__ float g_uc [B * NC];           // u . cand^T (computed in parallel with tail)
__device__ float g_cT [NC * H];
__device__ float g_cA [NC * H];
__device__ float g_w3a[H * H];
__device__ float g_Wc [512 * 384];
__device__ float g_bc [512];
__device__ float g_Wio[256 * 128];
__device__ float g_bio[256];
// fp16 operands for tensor-core tail (final error-compensated, candidates single)
__device__ __half g_fh [B * LP * H];
__device__ __half g_fl [B * LP * H];
__device__ __half g_cTh[NCP * H];
__device__ __half g_cAh[NCP * H];

// ---------------- mark session items ----------------
__global__ void k_mark(const int* __restrict__ items) {
    int i = blockIdx.x * blockDim.x + threadIdx.x;
    if (i < B * L) g_mark[items[i]] = 1;
}

// ---------------- edge scatter, vector red, filtered ----------------
__global__ void k_edge(const int* __restrict__ row, const int* __restrict__ col,
                       const float* __restrict__ w, const float* __restrict__ emb) {
    int i = blockIdx.x * blockDim.x + threadIdx.x;
    int e = i >> 5;
    int q = i & 31;
    if (e < E) {
        int r = row[e];
        if (g_mark[r]) {
            float ww = w[e];
            int c = col[e];
            float4 v = ((const float4*)(emb + c * H))[q];
            v.x *= ww; v.y *= ww; v.z *= ww; v.w *= ww;
            float* dst = &g_agg[r * H + q * 4];
            asm volatile("red.global.add.v4.f32 [%0], {%1, %2, %3, %4};"
                         :: "l"(dst), "f"(v.x), "f"(v.y), "f"(v.z), "f"(v.w)
                         : "memory");
        }
    }
}

// ---------------- transpose w3[:, :H] ----------------
__global__ void k_w3t(const float* __restrict__ w3) {
    int n = blockIdx.x, k = threadIdx.x;
    g_w3a[n * H + k] = w3[k * 3 * H + n];
}

// ---------------- build concat weights: Wc[512x384], Wio[256x128] ----------------
__global__ void k_prep(const float* __restrict__ liW, const float* __restrict__ lib,
                       const float* __restrict__ loW, const float* __restrict__ lob,
                       const float* __restrict__ w_ih, const float* __restrict__ w_hh,
                       const float* __restrict__ b_ih, const float* __restrict__ b_hh) {
    int n = blockIdx.x, k = threadIdx.x;   // k < 384
    if (n < 512) {
        int j = n & 127;
        int sec = n >> 7;                  // 0:r 1:z 2:i_n 3:h_n
        float v;
        if (sec <= 1) {
            int row = sec * 128 + j;
            v = (k < 256) ? w_ih[row * 256 + k] : w_hh[row * 128 + (k - 256)];
        } else if (sec == 2) {
            v = (k < 256) ? w_ih[(256 + j) * 256 + k] : 0.f;
        } else {
            v = (k < 256) ? 0.f : w_hh[(256 + j) * 128 + (k - 256)];
        }
        g_Wc[n * 384 + k] = v;
        if (k == 0) {
            float bb;
            if (sec == 0)      bb = b_ih[j] + b_hh[j];
            else if (sec == 1) bb = b_ih[128 + j] + b_hh[128 + j];
            else if (sec == 2) bb = b_ih[256 + j];
            else               bb = b_hh[256 + j];
            g_bc[n] = bb;
        }
    } else {
        int m = n - 512;                   // 0..255
        if (k < 128) {
            g_Wio[m * 128 + k] = (m < 128) ? liW[m * 128 + k] : loW[(m - 128) * 128 + k];
            if (k == 0) g_bio[m] = (m < 128) ? lib[m] : lob[m - 128];
        }
    }
}

// ---------------- generic tiled GEMM: C op= act(A[aidx[M],K] @ Bw[N,K]^T + bias) ----------------
__global__ void __launch_bounds__(256) k_gemm(const float* __restrict__ A,
                                              const float* __restrict__ Bw,
                                              const float* __restrict__ bias,
                                              float* __restrict__ C,
                                              int M, int N, int K, int relu,
                                              const int* __restrict__ aidx, int accum) {
    __shared__ float As[64][33];
    __shared__ float Bs[64][33];
    int m0 = blockIdx.y * 64, n0 = blockIdx.x * 64;
    int tid = threadIdx.x;
    int tx = tid & 15, ty = tid >> 4;
    float acc[4][4] = {};
    for (int k0 = 0; k0 < K; k0 += 32) {
        #pragma unroll
        for (int i = 0; i < 2; i++) {
            int f = tid + 256 * i;
            int m = f >> 3, k4 = f & 7;
            int gm = m0 + m;
            float4 v = make_float4(0.f, 0.f, 0.f, 0.f);
            if (gm < M) {
                int am = aidx ? aidx[gm] : gm;
                v = *(const float4*)&A[am * K + k0 + k4 * 4];
            }
            As[m][k4 * 4 + 0] = v.x; As[m][k4 * 4 + 1] = v.y;
            As[m][k4 * 4 + 2] = v.z; As[m][k4 * 4 + 3] = v.w;
        }
        #pragma unroll
        for (int i = 0; i < 2; i++) {
            int f = tid + 256 * i;
            int n = f >> 3, k4 = f & 7;
            int gn = n0 + n;
            float4 v = make_float4(0.f, 0.f, 0.f, 0.f);
            if (gn < N) v = *(const float4*)&Bw[gn * K + k0 + k4 * 4];
            Bs[n][k4 * 4 + 0] = v.x; Bs[n][k4 * 4 + 1] = v.y;
            Bs[n][k4 * 4 + 2] = v.z; Bs[n][k4 * 4 + 3] = v.w;
        }
        __syncthreads();
        #pragma unroll
        for (int k = 0; k < 32; k++) {
            float a[4], b[4];
            #pragma unroll
            for (int r = 0; r < 4; r++) a[r] = As[ty * 4 + r][k];
            #pragma unroll
            for (int c = 0; c < 4; c++) b[c] = Bs[tx * 4 + c][k];
            #pragma unroll
            for (int r = 0; r < 4; r++)
                #pragma unroll
                for (int c = 0; c < 4; c++)
                    acc[r][c] += a[r] * b[c];
        }
        __syncthreads();
    }
    #pragma unroll
    for (int r = 0; r < 4; r++) {
        int gm = m0 + ty * 4 + r;
        if (gm < M) {
            #pragma unroll
            for (int c = 0; c < 4; c++) {
                int gn = n0 + tx * 4 + c;
                if (gn < N) {
                    float v = acc[r][c] + (bias ? bias[gn] : 0.f);
                    if (relu) v = fmaxf(v, 0.f);
                    if (accum) C[gm * N + gn] += v;
                    else       C[gm * N + gn] = v;
                }
            }
        }
    }
}

// ---------------- final add: out += uc ----------------
__global__ void k_add(float* __restrict__ out) {
    int i = blockIdx.x * blockDim.x + threadIdx.x;
    if (i < B * NC) out[i] += g_uc[i];
}

// ---------------- inp = adj @ ao, + h0 gather, into g_cat ----------------
#define PROP_SMEM ((L * L + L * 256) * 4)
__global__ void k_prop(const float* __restrict__ adj, const int* __restrict__ items,
                       const float* __restrict__ emb) {
    extern __shared__ float psm[];
    float* sA  = psm;
    float* sin = psm + L * L;
    int b = blockIdx.x, t = threadIdx.x;   // 256 threads
    for (int i = t; i < L * L; i += 256) sA[i] = adj[b * L * L + i];
    for (int k = 0; k < L; k++) sin[k * 256 + t] = g_ao[(b * L + k) * 256 + t];
    __syncthreads();
    for (int l = 0; l < L; l++) {
        float acc = 0.f;
        #pragma unroll 10
        for (int k = 0; k < L; k++)
            acc += sA[l * L + k] * sin[k * 256 + t];
        g_cat[(b * L + l) * 384 + t] = acc;
    }
    for (int i = t; i < L * H; i += 256) {
        int l = i >> 7, tt = i & 127;
        g_cat[(b * L + l) * 384 + 256 + tt] = emb[items[b * L + l] * H + tt];
    }
}

// ---------------- GRU elementwise + relu(sg) + pos emb + final + last + fp16 split ----------------
__global__ void k_gru_elem(const int* __restrict__ items, const int* __restrict__ lens,
                           const float* __restrict__ pos_emb) {
    int i = blockIdx.x * blockDim.x + threadIdx.x;
    int bl = i >> 7, t = i & 127;
    int b = bl / L, l = bl % L;
    const float* g = g_gates + bl * 512;
    float r = 1.f / (1.f + expf(-g[t]));
    float z = 1.f / (1.f + expf(-g[128 + t]));
    float n = tanhf(g[256 + t] + r * g[384 + t]);
    float h0 = g_cat[bl * 384 + 256 + t];
    float hn = n + z * (h0 - n);
    int item = items[bl];
    int len  = lens[b];
    int rev  = (item == 0) ? 0 : (len - 1 - l);
    float fin = fmaxf(g_sg[i], 0.f) + hn + pos_emb[rev * H + t];
    g_final[i] = fin;
    __half fh = __float2half(fin);
    g_fh[(b * LP + l) * H + t] = fh;
    g_fl[(b * LP + l) * H + t] = __float2half(fin - __half2float(fh));
    if (l == len - 1) g_last[b * H + t] = fin;
}

// ---------------- candidate fp16 convert ----------------
__global__ void k_cvt_cand() {
    int i = blockIdx.x * blockDim.x + threadIdx.x;   // NCP*H
    int n = i >> 7;
    float vT = 0.f, vA = 0.f;
    if (n < NC) { vT = g_cT[i]; vA = g_cA[i]; }
    g_cTh[i] = __float2half(vT);
    g_cAh[i] = __float2half(vA);
}

// ---------------- attention readout -> g_u ----------------
#define ATTN_SMEM ((L * 2 * H + H + 8 * 64 + 3 * H) * 4 + 64 * 4)
__global__ void k_attn(const int* __restrict__ items,
                       const float* __restrict__ ipw, const float* __restrict__ ipb,
                       const float* __restrict__ opw, const float* __restrict__ opb,
                       const float* __restrict__ w3) {
    extern __shared__ float sm[];
    float* kvs = sm;
    float* qs  = kvs + L * 2 * H;
    float* att = qs + H;
    float* ctx = att + 8 * 64;
    float* sg  = ctx + H;
    float* ls  = sg + H;
    int*   its = (int*)(ls + H);

    int b = blockIdx.x, t = threadIdx.x;
    for (int i = t; i < L * 2 * H; i += 256) kvs[i] = g_kv[b * L * 2 * H + i];
    if (t < H) ls[t] = g_last[b * H + t];
    if (t < L) its[t] = items[b * L + t];
    __syncthreads();

    if (t < H) {
        float a = ipb[t];
        const float* w = ipw + t * H;
        #pragma unroll 8
        for (int k = 0; k < H; k++) a += ls[k] * w[k];
        qs[t] = a;
    }
    __syncthreads();
    for (int i = t; i < 8 * L; i += 256) {
        int hd = i / L, l = i % L;
        float a = 0.f;
        #pragma unroll
        for (int d = 0; d < 16; d++) a += qs[hd * 16 + d] * kvs[l * 2 * H + hd * 16 + d];
        att[hd * 64 + l] = (its[l] == 0) ? -INFINITY : a * 0.25f;
    }
    __syncthreads();
    if (t < 8) {
        float m = -INFINITY;
        for (int l = 0; l < L; l++) m = fmaxf(m, att[t * 64 + l]);
        float s = 0.f;
        for (int l = 0; l < L; l++) {
            float e = expf(att[t * 64 + l] - m);
            att[t * 64 + l] = e;
            s += e;
        }
        float inv = 1.f / s;
        for (int l = 0; l < L; l++) att[t * 64 + l] *= inv;
    }
    __syncthreads();
    if (t < H) {
        int hd = t / 16;
        float c = 0.f;
        for (int l = 0; l < L; l++) c += att[hd * 64 + l] * kvs[l * 2 * H + H + t];
        ctx[t] = c;
    }
    __syncthreads();
    if (t < H) {
        float a = opb[t];
        const float* w = opw + t * H;
        #pragma unroll 8
        for (int k = 0; k < H; k++) a += ctx[k] * w[k];
        sg[t] = a;
    }
    __syncthreads();
    if (t < H) {
        float u = 0.f;
        const float* w1 = w3 + t * 3 * H + H;
        const float* w2 = w3 + t * 3 * H + 2 * H;
        #pragma unroll 8
        for (int k = 0; k < H; k++) u += ls[k] * w1[k] + sg[k] * w2[k];
        g_u[b * H + t] = u;
    }
}

// ---------------- tensor-core tail (persistent, online softmax, low reg) ----------------
// smem: cT[128x128 fp16]=32K | cA=32K | F=[fh|fl][64x256 fp16]=32K | its
#define T_CT  0
#define T_CA  32768
#define T_F   65536
#define T_ITS 98304
#define TAIL_SMEM (T_ITS + 256 + 16)

__device__ __forceinline__ void ldsm_x4(uint32_t addr, uint32_t& r0, uint32_t& r1,
                                        uint32_t& r2, uint32_t& r3) {
    asm volatile("ldmatrix.sync.aligned.m8n8.x4.shared.b16 {%0,%1,%2,%3}, [%4];"
                 : "=r"(r0), "=r"(r1), "=r"(r2), "=r"(r3) : "r"(addr));
}
__device__ __forceinline__ void mma_fp16(float* d, uint32_t a0, uint32_t a1,
                                         uint32_t a2, uint32_t a3,
                                         uint32_t b0, uint32_t b1) {
    asm volatile(
        "mma.sync.aligned.m16n8k16.row.col.f32.f16.f16.f32 "
        "{%0,%1,%2,%3}, {%4,%5,%6,%7}, {%8,%9}, {%0,%1,%2,%3};"
        : "+f"(d[0]), "+f"(d[1]), "+f"(d[2]), "+f"(d[3])
        : "r"(a0), "r"(a1), "r"(a2), "r"(a3), "r"(b0), "r"(b1));
}
__device__ __forceinline__ uint32_t swz(uint32_t base, int row, int ch, int rs_ch) {
    return base + (uint32_t)(row * rs_ch * 16 + (((ch) ^ (row & 7)) << 4));
}

__global__ void __launch_bounds__(256, 2) k_tail(const int* __restrict__ items,
                                                 float* __restrict__ out) {
    extern __shared__ char smc[];
    uint32_t sb = (uint32_t)__cvta_generic_to_shared(smc);
    int* its = (int*)(smc + T_ITS);
    unsigned* s_item = (unsigned*)(smc + T_ITS + 256);

    int t = threadIdx.x;
    int w = t >> 5, lane = t & 31;
    int mat = lane >> 3, rin = lane & 7;
    int g = lane >> 2, tg = lane & 3;
    int Rm = 16 * w;

    int row_a = Rm + rin + ((mat & 1) << 3);
    int row_b = rin + ((mat >> 1) << 3);

    int cur_n0 = -1;
    for (;;) {
        if (t == 0) *s_item = atomicAdd(&g_ticket, 1u);
        __syncthreads();
        unsigned item = *s_item;
        __syncthreads();
        if (item >= NITEMS) break;
        int n0 = (int)(item >> 3) * 128;
        int bg = (int)(item & 7) * 8;

        // ---- (re)load candidate tiles if n-tile changed ----
        if (n0 != cur_n0) {
            cur_n0 = n0;
            #pragma unroll
            for (int it = 0; it < 8; it++) {
                int idx = t + 256 * it;
                int r = idx >> 4, c = idx & 15;
                uint4 v = *(const uint4*)&g_cTh[(n0 + r) * H + c * 8];
                *(uint4*)(smc + T_CT + r * 256 + ((c ^ (r & 7)) << 4)) = v;
            }
            #pragma unroll
            for (int it = 0; it < 8; it++) {
                int idx = t + 256 * it;
                int r = idx >> 4, c = idx & 15;
                uint4 v = *(const uint4*)&g_cAh[(n0 + r) * H + c * 8];
                *(uint4*)(smc + T_CA + r * 256 + ((c ^ (r & 7)) << 4)) = v;
            }
        }

        for (int bi = 0; bi < 8; bi++) {
            int b = bg + bi;
            // ---- load F = [fh|fl] for this batch ----
            #pragma unroll
            for (int it = 0; it < 8; it++) {
                int idx = t + 256 * it;
                int r = idx >> 5, c = idx & 31;
                const __half* src = (c < 16) ? &g_fh[(b * LP + r) * H + c * 8]
                                             : &g_fl[(b * LP + r) * H + (c - 16) * 8];
                uint4 v = *(const uint4*)src;
                *(uint4*)(smc + T_F + r * 512 + ((c ^ (r & 7)) << 4)) = v;
            }
            if (t < 64) its[t] = (t < L) ? items[b * L + t] : 0;
            __syncthreads();

            // online-softmax state for rows {Rm+g, Rm+g+8}
            float om[2] = { -INFINITY, -INFINITY };
            float os[2] = { 0.f, 0.f };
            float oa[2] = { 0.f, 0.f };

            #pragma unroll
            for (int lhalf = 0; lhalf < 2; lhalf++) {
                float Sacc[4][4] = {}, Gacc[4][4] = {};
                for (int kc = 0; kc < 8; kc++) {
                    uint32_t aT[4], aA[4];
                    int ch_a = 2 * kc + (mat >> 1);
                    ldsm_x4(swz(sb + T_CT, row_a, ch_a, 16), aT[0], aT[1], aT[2], aT[3]);
                    ldsm_x4(swz(sb + T_CA, row_a, ch_a, 16), aA[0], aA[1], aA[2], aA[3]);
                    uint32_t bf[2][4];
                    // fh half -> S and G
                    #pragma unroll
                    for (int nh2 = 0; nh2 < 2; nh2++) {
                        int nh = 2 * lhalf + nh2;
                        ldsm_x4(swz(sb + T_F, 16 * nh + row_b, 2 * kc + (mat & 1), 32),
                                bf[nh2][0], bf[nh2][1], bf[nh2][2], bf[nh2][3]);
                    }
                    #pragma unroll
                    for (int jl = 0; jl < 4; jl++) {
                        uint32_t b0 = bf[jl >> 1][2 * (jl & 1)], b1 = bf[jl >> 1][2 * (jl & 1) + 1];
                        mma_fp16(Sacc[jl], aT[0], aT[1], aT[2], aT[3], b0, b1);
                        mma_fp16(Gacc[jl], aA[0], aA[1], aA[2], aA[3], b0, b1);
                    }
                    // fl half -> G only
                    #pragma unroll
                    for (int nh2 = 0; nh2 < 2; nh2++) {
                        int nh = 2 * lhalf + nh2;
                        ldsm_x4(swz(sb + T_F, 16 * nh + row_b, 16 + 2 * kc + (mat & 1), 32),
                                bf[nh2][0], bf[nh2][1], bf[nh2][2], bf[nh2][3]);
                    }
                    #pragma unroll
                    for (int jl = 0; jl < 4; jl++) {
                        uint32_t b0 = bf[jl >> 1][2 * (jl & 1)], b1 = bf[jl >> 1][2 * (jl & 1) + 1];
                        mma_fp16(Gacc[jl], aA[0], aA[1], aA[2], aA[3], b0, b1);
                    }
                }
                // fold this half into online state
                #pragma unroll
                for (int h = 0; h < 2; h++) {
                    float mloc = -INFINITY;
                    unsigned mk = 0;
                    #pragma unroll
                    for (int jl = 0; jl < 4; jl++) {
                        int lb = lhalf * 32 + 8 * jl + 2 * tg;
                        if (its[lb]) { mk |= (1u << (2 * jl)); mloc = fmaxf(mloc, Sacc[jl][2 * h]); }
                        if (its[lb + 1]) { mk |= (1u << (2 * jl + 1)); mloc = fmaxf(mloc, Sacc[jl][2 * h + 1]); }
                    }
                    float newm = fmaxf(fmaxf(om[h], mloc), -1e30f);
                    float sc = __expf(om[h] - newm);   // om=-inf -> 0
                    float s2 = os[h] * sc, a2 = oa[h] * sc;
                    #pragma unroll
                    for (int jl = 0; jl < 4; jl++) {
                        if (mk & (1u << (2 * jl))) {
                            float e = __expf(Sacc[jl][2 * h] - newm);
                            s2 += e; a2 += e * Gacc[jl][2 * h];
                        }
                        if (mk & (1u << (2 * jl + 1))) {
                            float e = __expf(Sacc[jl][2 * h + 1] - newm);
                            s2 += e; a2 += e * Gacc[jl][2 * h + 1];
                        }
                    }
                    om[h] = newm; os[h] = s2; oa[h] = a2;
                }
            }

            // quad merge (xor 1, 2) with online-merge formula
            #pragma unroll
            for (int h = 0; h < 2; h++) {
                #pragma unroll
                for (int d = 1; d <= 2; d <<= 1) {
                    float pm = __shfl_xor_sync(0xFFFFFFFF, om[h], d);
                    float ps = __shfl_xor_sync(0xFFFFFFFF, os[h], d);
                    float pa = __shfl_xor_sync(0xFFFFFFFF, oa[h], d);
                    float newm = fmaxf(fmaxf(om[h], pm), -1e30f);
                    float sc1 = __expf(om[h] - newm);
                    float sc2 = __expf(pm - newm);
                    os[h] = os[h] * sc1 + ps * sc2;
                    oa[h] = oa[h] * sc1 + pa * sc2;
                    om[h] = newm;
                }
                if (tg == 0) {
                    int gn = n0 + Rm + g + 8 * h;
                    if (gn < NC) out[b * NC + gn] = oa[h] / os[h];
                }
            }
            __syncthreads();   // protect F/its before next batch overwrites
        }
    }
}

// ---------------- host launcher ----------------
extern "C" void kernel_launch(void* const* d_in, const int* in_sizes, int n_in,
                              void* d_out, int out_size) {
    const int*   items = (const int*)d_in[0];
    const int*   lens  = (const int*)d_in[1];
    const float* adj   = (const float*)d_in[2];
    const int*   erow  = (const int*)d_in[3];
    const int*   ecol  = (const int*)d_in[4];
    const float* ew    = (const float*)d_in[5];
    const float* emb   = (const float*)d_in[6];
    const float* pos   = (const float*)d_in[7];
    const float* gW    = (const float*)d_in[8];
    const float* gb    = (const float*)d_in[9];
    const float* liW   = (const float*)d_in[10];
    const float* lib   = (const float*)d_in[11];
    const float* loW   = (const float*)d_in[12];
    const float* lob   = (const float*)d_in[13];
    const float* w_ih  = (const float*)d_in[14];
    const float* w_hh  = (const float*)d_in[15];
    const float* b_ih  = (const float*)d_in[16];
    const float* b_hh  = (const float*)d_in[17];
    const float* ipw   = (const float*)d_in[18];
    const float* ipb   = (const float*)d_in[19];
    const float* opw   = (const float*)d_in[20];
    const float* opb   = (const float*)d_in[21];
    const float* wt    = (const float*)d_in[22];
    const float* w3    = (const float*)d_in[23];
    float* out = (float*)d_out;

    // one-time resource creation (NOT during graph capture; first call only)
    static bool s_init = false;
    static cudaStream_t s1, s2, s3;
    static cudaEvent_t evRoot, evCand, evGru, evGE, evUC;
    if (!s_init) {
        cudaStreamCreateWithFlags(&s1, cudaStreamNonBlocking);
        cudaStreamCreateWithFlags(&s2, cudaStreamNonBlocking);
        cudaStreamCreateWithFlags(&s3, cudaStreamNonBlocking);
        cudaEventCreateWithFlags(&evRoot, cudaEventDisableTiming);
        cudaEventCreateWithFlags(&evCand, cudaEventDisableTiming);
        cudaEventCreateWithFlags(&evGru,  cudaEventDisableTiming);
        cudaEventCreateWithFlags(&evGE,   cudaEventDisableTiming);
        cudaEventCreateWithFlags(&evUC,   cudaEventDisableTiming);
        cudaFuncSetAttribute(k_attn, cudaFuncAttributeMaxDynamicSharedMemorySize, ATTN_SMEM);
        cudaFuncSetAttribute(k_tail, cudaFuncAttributeMaxDynamicSharedMemorySize, TAIL_SMEM);
        cudaFuncSetAttribute(k_prop, cudaFuncAttributeMaxDynamicSharedMemorySize, PROP_SMEM);
        s_init = true;
    }

    float* p_agg;   cudaGetSymbolAddress((void**)&p_agg,   g_agg);
    int*   p_mark;  cudaGetSymbolAddress((void**)&p_mark,  g_mark);
    unsigned* p_tk; cudaGetSymbolAddress((void**)&p_tk,    g_ticket);
    float* p_sg;    cudaGetSymbolAddress((void**)&p_sg,    g_sg);
    float* p_ao;    cudaGetSymbolAddress((void**)&p_ao,    g_ao);
    float* p_cat;   cudaGetSymbolAddress((void**)&p_cat,   g_cat);
    float* p_gates; cudaGetSymbolAddress((void**)&p_gates, g_gates);
    float* p_final; cudaGetSymbolAddress((void**)&p_final, g_final);
    float* p_kv;    cudaGetSymbolAddress((void**)&p_kv,    g_kv);
    float* p_u;     cudaGetSymbolAddress((void**)&p_u,     g_u);
    float* p_uc;    cudaGetSymbolAddress((void**)&p_uc,    g_uc);
    float* p_cT;    cudaGetSymbolAddress((void**)&p_cT,    g_cT);
    float* p_cA;    cudaGetSymbolAddress((void**)&p_cA,    g_cA);
    float* p_w3a;   cudaGetSymbolAddress((void**)&p_w3a,   g_w3a);
    float* p_Wc;    cudaGetSymbolAddress((void**)&p_Wc,    g_Wc);
    float* p_bc;    cudaGetSymbolAddress((void**)&p_bc,    g_bc);
    float* p_Wio;   cudaGetSymbolAddress((void**)&p_Wio,   g_Wio);
    float* p_bio;   cudaGetSymbolAddress((void**)&p_bio,   g_bio);
    void*  p_fh;    cudaGetSymbolAddress(&p_fh,  g_fh);
    void*  p_fl;    cudaGetSymbolAddress(&p_fl,  g_fl);

    const int M = B * L;   // 3200

    cudaEventRecord(evRoot, 0);
    cudaStreamWaitEvent(s1, evRoot, 0);
    cudaStreamWaitEvent(s2, evRoot, 0);

    // ---- s1: candidate chain ----
    k_w3t<<<H, H, 0, s1>>>(w3);
    {
        dim3 gC(2, (NC + 63) / 64);
        k_gemm<<<gC, 256, 0, s1>>>(emb + H, wt,    (const float*)nullptr, p_cT, NC, H, H, 0, nullptr, 0);
        k_gemm<<<gC, 256, 0, s1>>>(emb + H, p_w3a, (const float*)nullptr, p_cA, NC, H, H, 0, nullptr, 0);
    }
    k_cvt_cand<<<(NCP * H) / 256, 256, 0, s1>>>();
    cudaEventRecord(evCand, s1);

    // ---- s2: GRU chain (independent of edge scatter) ----
    k_prep<<<768, 384, 0, s2>>>(liW, lib, loW, lob, w_ih, w_hh, b_ih, b_hh);
    {
        dim3 gA(4, (M + 63) / 64);    // N=256: [ain|aout] = emb[items] @ Wio^T
        k_gemm<<<gA, 256, 0, s2>>>(emb, p_Wio, p_bio, p_ao, M, 256, H, 0, items, 0);
    }
    k_prop<<<B, 256, PROP_SMEM, s2>>>(adj, items, emb);
    {
        dim3 gG(8, (M + 63) / 64);    // N=512: gates = cat @ Wc^T
        k_gemm<<<gG, 256, 0, s2>>>(p_cat, p_Wc, p_bc, p_gates, M, 512, 384, 0, nullptr, 0);
    }
    cudaEventRecord(evGru, s2);

    // ---- s0: edge scatter + sg ----
    cudaMemsetAsync(p_agg, 0, NI * H * sizeof(float));
    cudaMemsetAsync(p_mark, 0, NI * sizeof(int));
    cudaMemsetAsync(p_tk, 0, sizeof(unsigned));
    cudaMemsetAsync(p_fh, 0, B * LP * H * sizeof(__half));
    cudaMemsetAsync(p_fl, 0, B * LP * H * sizeof(__half));
    k_mark<<<(B * L + 255) / 256, 256>>>(items);
    k_edge<<<(E * 32 + 255) / 256, 256>>>(erow, ecol, ew, emb);
    {
        dim3 gS(2, (M + 63) / 64);    // sg_pre = agg[items] @ gW^T + gb (relu deferred)
        k_gemm<<<gS, 256>>>(p_agg, gW, gb, p_sg, M, H, H, 0, items, 0);
    }

    // join gru chain -> elementwise
    cudaStreamWaitEvent(0, evGru, 0);
    k_gru_elem<<<(M * H) / 256, 256>>>(items, lens, pos);
    cudaEventRecord(evGE, 0);

    // ---- s3: attention branch + uc GEMM (runs concurrently with tail) ----
    cudaStreamWaitEvent(s3, evGE, 0);
    {
        dim3 gKV(4, (M + 63) / 64);
        k_gemm<<<gKV, 256, 0, s3>>>(p_final, ipw + H * H, ipb + H, p_kv, M, 2 * H, H, 0, nullptr, 0);
    }
    k_attn<<<B, 256, ATTN_SMEM, s3>>>(items, ipw, ipb, opw, opb, w3);
    {
        dim3 gU((NC + 63) / 64, 1);   // uc = u @ cand^T -> g_uc (separate buffer)
        k_gemm<<<gU, 256, 0, s3>>>(p_u, emb + H, (const float*)nullptr, p_uc, B, NC, H, 0, nullptr, 0);
    }
    cudaEventRecord(evUC, s3);

    // ---- s0: persistent fp16 mma tail (writes scores), then cheap add ----
    cudaStreamWaitEvent(0, evCand, 0);
    k_tail<<<296, 256, TAIL_SMEM>>>(items, out);

    cudaStreamWaitEvent(0, evUC, 0);
    k_add<<<(B * NC + 255) / 256, 256>>>(out);
}

// round 12
// speedup vs baseline: 1.0769x; 1.0769x over previous
#include <cuda_runtime.h>
#include <cuda_bf16.h>
#include <cuda_fp16.h>
#include <math.h>
#include <stdint.h>

#define NI 10000
#define H  128
#define L  50
#define B  64
#define E  160000
#define NC 9999
#define NCP 10112     // NC padded to 128*79
#define LP 64         // L padded for MMA

// ---------------- persistent device scratch ----------------
__device__ float g_agg[NI * H];
__device__ int   g_mark[NI];
__device__ float g_sg [B * L * H];        // pre-relu
__device__ float g_ao [B * L * 256];      // [ain|aout]
__device__ float g_cat[B * L * 384];      // [inp(256) | h0(128)]
__device__ float g_gates[B * L * 512];    // [r_sum | z_sum | i_n | h_n]
__device__ float g_final[B * L * H];
__device__ float g_kv [B * L * 2 * H];
__device__ float g_last[B * H];
__device__ float g_u  [B * H];
__device__ float g_uc [B * NC];
__device__ float g_cT [NC * H];
__device__ float g_cA [NC * H];
__device__ float g_bc [512];
__device__ float g_bio[256];
// fp16 split operand buffers for tensor-core GEMMs
__device__ __half g_cAh1[NC * H],  g_cAl1[NC * H];    // candidates (emb[1:])
__device__ __half g_Ah2[B * L * 384], g_Al2[B * L * 384]; // cat
__device__ __half g_Ah3[B * L * H], g_Al3[B * L * H]; // emb[items]
__device__ __half g_Ah4[B * L * H], g_Al4[B * L * H]; // agg[items]
__device__ __half g_fch[B * L * H], g_fcl[B * L * H]; // final compact
// fp16 split weights
__device__ __half g_gWh[H * H],   g_gWl[H * H];
__device__ __half g_kvwh[256 * H], g_kvwl[256 * H];
__device__ __half g_wth[H * H],   g_wtl[H * H];
__device__ __half g_w3h[H * H],   g_w3l[H * H];       // w3[:, :H]^T
__device__ __half g_Wch[512 * 384], g_Wcl[512 * 384];
__device__ __half g_Wioh[256 * H], g_Wiol[256 * H];
// fp16 operands for tail (final padded, candidates single)
__device__ __half g_fh [B * LP * H];
__device__ __half g_fl [B * LP * H];
__device__ __half g_cTh[NCP * H];
__device__ __half g_cAh[NCP * H];

// ---------------- mma helpers (shared by gemm16 and tail) ----------------
__device__ __forceinline__ void ldsm_x4(uint32_t addr, uint32_t& r0, uint32_t& r1,
                                        uint32_t& r2, uint32_t& r3) {
    asm volatile("ldmatrix.sync.aligned.m8n8.x4.shared.b16 {%0,%1,%2,%3}, [%4];"
                 : "=r"(r0), "=r"(r1), "=r"(r2), "=r"(r3) : "r"(addr));
}
__device__ __forceinline__ void mma_fp16(float* d, uint32_t a0, uint32_t a1,
                                         uint32_t a2, uint32_t a3,
                                         uint32_t b0, uint32_t b1) {
    asm volatile(
        "mma.sync.aligned.m16n8k16.row.col.f32.f16.f16.f32 "
        "{%0,%1,%2,%3}, {%4,%5,%6,%7}, {%8,%9}, {%0,%1,%2,%3};"
        : "+f"(d[0]), "+f"(d[1]), "+f"(d[2]), "+f"(d[3])
        : "r"(a0), "r"(a1), "r"(a2), "r"(a3), "r"(b0), "r"(b1));
}
__device__ __forceinline__ uint32_t swz(uint32_t base, int row, int ch, int rs_ch) {
    return base + (uint32_t)(row * rs_ch * 16 + (((ch) ^ (row & 7)) << 4));
}

// ---------------- mark session items ----------------
__global__ void k_mark(const int* __restrict__ items) {
    int i = blockIdx.x * blockDim.x + threadIdx.x;
    if (i < B * L) g_mark[items[i]] = 1;
}

// ---------------- edge scatter ----------------
__global__ void k_edge(const int* __restrict__ row, const int* __restrict__ col,
                       const float* __restrict__ w, const float* __restrict__ emb) {
    int i = blockIdx.x * blockDim.x + threadIdx.x;
    int e = i >> 5;
    int q = i & 31;
    if (e < E) {
        int r = row[e];
        if (g_mark[r]) {
            float ww = w[e];
            int c = col[e];
            float4 v = ((const float4*)(emb + c * H))[q];
            v.x *= ww; v.y *= ww; v.z *= ww; v.w *= ww;
            float* dst = &g_agg[r * H + q * 4];
            asm volatile("red.global.add.v4.f32 [%0], {%1, %2, %3, %4};"
                         :: "l"(dst), "f"(v.x), "f"(v.y), "f"(v.z), "f"(v.w)
                         : "memory");
        }
    }
}

// ---------------- fp32 -> fp16 h/l split with optional row gather ----------------
__global__ void k_cvtA(const float* __restrict__ src, const int* __restrict__ aidx,
                       __half* __restrict__ oh, __half* __restrict__ ol, int M, int K) {
    int i = blockIdx.x * blockDim.x + threadIdx.x;
    if (i < M * K) {
        int row = i / K, colk = i - row * K;
        int ar = aidx ? aidx[row] : row;
        float v = src[ar * K + colk];
        __half h = __float2half(v);
        oh[i] = h;
        ol[i] = __float2half(v - __half2float(h));
    }
}

// ---------------- weight converts ----------------
__global__ void k_cvtw0(const float* __restrict__ gW, const float* __restrict__ kvw) {
    int n = blockIdx.x, k = threadIdx.x;   // 384 x 128
    float v;
    __half *oh, *ol;
    int i;
    if (n < 128) { v = gW[n * H + k]; i = n * H + k; oh = g_gWh; ol = g_gWl; }
    else { int m = n - 128; v = kvw[m * H + k]; i = m * H + k; oh = g_kvwh; ol = g_kvwl; }
    __half h = __float2half(v);
    oh[i] = h;
    ol[i] = __float2half(v - __half2float(h));
}
__global__ void k_cvtw1(const float* __restrict__ wt, const float* __restrict__ w3) {
    int n = blockIdx.x, k = threadIdx.x;   // 256 x 128
    float v;
    __half *oh, *ol;
    int i;
    if (n < 128) { v = wt[n * H + k]; i = n * H + k; oh = g_wth; ol = g_wtl; }
    else { int m = n - 128; v = w3[k * 384 + m]; i = m * H + k; oh = g_w3h; ol = g_w3l; }
    __half h = __float2half(v);
    oh[i] = h;
    ol[i] = __float2half(v - __half2float(h));
}

// ---------------- build concat weights (fp16 h/l) ----------------
__global__ void k_prep(const float* __restrict__ liW, const float* __restrict__ lib,
                       const float* __restrict__ loW, const float* __restrict__ lob,
                       const float* __restrict__ w_ih, const float* __restrict__ w_hh,
                       const float* __restrict__ b_ih, const float* __restrict__ b_hh) {
    int n = blockIdx.x, k = threadIdx.x;   // k < 384
    if (n < 512) {
        int j = n & 127;
        int sec = n >> 7;
        float v;
        if (sec <= 1) {
            int row = sec * 128 + j;
            v = (k < 256) ? w_ih[row * 256 + k] : w_hh[row * 128 + (k - 256)];
        } else if (sec == 2) {
            v = (k < 256) ? w_ih[(256 + j) * 256 + k] : 0.f;
        } else {
            v = (k < 256) ? 0.f : w_hh[(256 + j) * 128 + (k - 256)];
        }
        __half h = __float2half(v);
        g_Wch[n * 384 + k] = h;
        g_Wcl[n * 384 + k] = __float2half(v - __half2float(h));
        if (k == 0) {
            float bb;
            if (sec == 0)      bb = b_ih[j] + b_hh[j];
            else if (sec == 1) bb = b_ih[128 + j] + b_hh[128 + j];
            else if (sec == 2) bb = b_ih[256 + j];
            else               bb = b_hh[256 + j];
            g_bc[n] = bb;
        }
    } else {
        int m = n - 512;
        if (k < 128) {
            float v = (m < 128) ? liW[m * 128 + k] : loW[(m - 128) * 128 + k];
            __half h = __float2half(v);
            g_Wioh[m * 128 + k] = h;
            g_Wiol[m * 128 + k] = __float2half(v - __half2float(h));
            if (k == 0) g_bio[m] = (m < 128) ? lib[m] : lob[m - 128];
        }
    }
}

// ---------------- tensor-core GEMM: C[M,N] = (Ah+Al)@(Bh+Bl)^T + bias (3-term) ----------------
#define G16_SMEM 49152
__global__ void __launch_bounds__(256) k_gemm16(
    const __half* __restrict__ Ah, const __half* __restrict__ Al,
    const __half* __restrict__ Bh, const __half* __restrict__ Bl,
    const float* __restrict__ bias, float* __restrict__ C,
    int M, int N, int K) {
    extern __shared__ char smc[];
    uint32_t sb = (uint32_t)__cvta_generic_to_shared(smc);
    const int SA_H = 0, SA_L = 16384, SB_H = 32768, SB_L = 40960;
    int t = threadIdx.x;
    int w = t >> 5, lane = t & 31;
    int mat = lane >> 3, rin = lane & 7;
    int g = lane >> 2, tg = lane & 3;
    int Rm = 16 * w;
    int m0 = blockIdx.y * 128, n0 = blockIdx.x * 64;
    int row_a = Rm + rin + ((mat & 1) << 3);
    int row_b = rin + ((mat >> 1) << 3);

    float acc[8][4] = {};
    for (int k0 = 0; k0 < K; k0 += 64) {
        #pragma unroll
        for (int it = 0; it < 4; it++) {
            int idx = t + 256 * it;      // 1024: 128 rows x 8 chunks
            int r = idx >> 3, c = idx & 7;
            int gm = m0 + r;
            uint4 vh = make_uint4(0, 0, 0, 0), vl = vh;
            if (gm < M) {
                vh = *(const uint4*)&Ah[gm * K + k0 + c * 8];
                vl = *(const uint4*)&Al[gm * K + k0 + c * 8];
            }
            uint32_t off = (uint32_t)(r * 128 + ((c ^ (r & 7)) << 4));
            *(uint4*)(smc + SA_H + off) = vh;
            *(uint4*)(smc + SA_L + off) = vl;
        }
        #pragma unroll
        for (int it = 0; it < 2; it++) {
            int idx = t + 256 * it;      // 512: 64 rows x 8 chunks
            int r = idx >> 3, c = idx & 7;
            int gn = n0 + r;
            uint4 vh = make_uint4(0, 0, 0, 0), vl = vh;
            if (gn < N) {
                vh = *(const uint4*)&Bh[gn * K + k0 + c * 8];
                vl = *(const uint4*)&Bl[gn * K + k0 + c * 8];
            }
            uint32_t off = (uint32_t)(r * 128 + ((c ^ (r & 7)) << 4));
            *(uint4*)(smc + SB_H + off) = vh;
            *(uint4*)(smc + SB_L + off) = vl;
        }
        __syncthreads();
        #pragma unroll
        for (int k16 = 0; k16 < 4; k16++) {
            uint32_t aH[4], aL[4];
            int ca = 2 * k16 + (mat >> 1);
            ldsm_x4(swz(sb + SA_H, row_a, ca, 8), aH[0], aH[1], aH[2], aH[3]);
            ldsm_x4(swz(sb + SA_L, row_a, ca, 8), aL[0], aL[1], aL[2], aL[3]);
            int cb = 2 * k16 + (mat & 1);
            uint32_t bH[4][4], bL[4][4];
            #pragma unroll
            for (int nh = 0; nh < 4; nh++) {
                ldsm_x4(swz(sb + SB_H, 16 * nh + row_b, cb, 8),
                        bH[nh][0], bH[nh][1], bH[nh][2], bH[nh][3]);
                ldsm_x4(swz(sb + SB_L, 16 * nh + row_b, cb, 8),
                        bL[nh][0], bL[nh][1], bL[nh][2], bL[nh][3]);
            }
            #pragma unroll
            for (int j = 0; j < 8; j++) {
                uint32_t h0 = bH[j >> 1][2 * (j & 1)], h1 = bH[j >> 1][2 * (j & 1) + 1];
                uint32_t l0 = bL[j >> 1][2 * (j & 1)], l1 = bL[j >> 1][2 * (j & 1) + 1];
                mma_fp16(acc[j], aH[0], aH[1], aH[2], aH[3], h0, h1);
                mma_fp16(acc[j], aL[0], aL[1], aL[2], aL[3], h0, h1);
                mma_fp16(acc[j], aH[0], aH[1], aH[2], aH[3], l0, l1);
            }
        }
        __syncthreads();
    }
    #pragma unroll
    for (int j = 0; j < 8; j++) {
        int gn = n0 + 8 * j + 2 * tg;
        if (gn < N) {
            float b0 = bias ? bias[gn] : 0.f;
            float b1 = bias ? bias[gn + 1] : 0.f;
            int gm0 = m0 + Rm + g;
            if (gm0 < M)
                *(float2*)&C[gm0 * N + gn] = make_float2(acc[j][0] + b0, acc[j][1] + b1);
            if (gm0 + 8 < M)
                *(float2*)&C[(gm0 + 8) * N + gn] = make_float2(acc[j][2] + b0, acc[j][3] + b1);
        }
    }
}

// ---------------- scalar GEMM (kept for uc only) ----------------
__global__ void __launch_bounds__(256) k_gemm(const float* __restrict__ A,
                                              const float* __restrict__ Bw,
                                              float* __restrict__ C,
                                              int M, int N, int K) {
    __shared__ float As[64][33];
    __shared__ float Bs[64][33];
    int m0 = blockIdx.y * 64, n0 = blockIdx.x * 64;
    int tid = threadIdx.x;
    int tx = tid & 15, ty = tid >> 4;
    float acc[4][4] = {};
    for (int k0 = 0; k0 < K; k0 += 32) {
        #pragma unroll
        for (int i = 0; i < 2; i++) {
            int f = tid + 256 * i;
            int m = f >> 3, k4 = f & 7;
            int gm = m0 + m;
            float4 v = make_float4(0.f, 0.f, 0.f, 0.f);
            if (gm < M) v = *(const float4*)&A[gm * K + k0 + k4 * 4];
            As[m][k4 * 4 + 0] = v.x; As[m][k4 * 4 + 1] = v.y;
            As[m][k4 * 4 + 2] = v.z; As[m][k4 * 4 + 3] = v.w;
        }
        #pragma unroll
        for (int i = 0; i < 2; i++) {
            int f = tid + 256 * i;
            int n = f >> 3, k4 = f & 7;
            int gn = n0 + n;
            float4 v = make_float4(0.f, 0.f, 0.f, 0.f);
            if (gn < N) v = *(const float4*)&Bw[gn * K + k0 + k4 * 4];
            Bs[n][k4 * 4 + 0] = v.x; Bs[n][k4 * 4 + 1] = v.y;
            Bs[n][k4 * 4 + 2] = v.z; Bs[n][k4 * 4 + 3] = v.w;
        }
        __syncthreads();
        #pragma unroll
        for (int k = 0; k < 32; k++) {
            float a[4], b[4];
            #pragma unroll
            for (int r = 0; r < 4; r++) a[r] = As[ty * 4 + r][k];
            #pragma unroll
            for (int c = 0; c < 4; c++) b[c] = Bs[tx * 4 + c][k];
            #pragma unroll
            for (int r = 0; r < 4; r++)
                #pragma unroll
                for (int c = 0; c < 4; c++)
                    acc[r][c] += a[r] * b[c];
        }
        __syncthreads();
    }
    #pragma unroll
    for (int r = 0; r < 4; r++) {
        int gm = m0 + ty * 4 + r;
        if (gm < M) {
            #pragma unroll
            for (int c = 0; c < 4; c++) {
                int gn = n0 + tx * 4 + c;
                if (gn < N) C[gm * N + gn] = acc[r][c];
            }
        }
    }
}

// ---------------- final add ----------------
__global__ void k_add(float* __restrict__ out) {
    int i = blockIdx.x * blockDim.x + threadIdx.x;
    if (i < B * NC) out[i] += g_uc[i];
}

// ---------------- inp = adj @ ao, + h0 gather, into g_cat ----------------
#define PROP_SMEM ((L * L + L * 256) * 4)
__global__ void k_prop(const float* __restrict__ adj, const int* __restrict__ items,
                       const float* __restrict__ emb) {
    extern __shared__ float psm[];
    float* sA  = psm;
    float* sin = psm + L * L;
    int b = blockIdx.x, t = threadIdx.x;
    for (int i = t; i < L * L; i += 256) sA[i] = adj[b * L * L + i];
    for (int k = 0; k < L; k++) sin[k * 256 + t] = g_ao[(b * L + k) * 256 + t];
    __syncthreads();
    for (int l = 0; l < L; l++) {
        float acc = 0.f;
        #pragma unroll 10
        for (int k = 0; k < L; k++)
            acc += sA[l * L + k] * sin[k * 256 + t];
        g_cat[(b * L + l) * 384 + t] = acc;
    }
    for (int i = t; i < L * H; i += 256) {
        int l = i >> 7, tt = i & 127;
        g_cat[(b * L + l) * 384 + 256 + tt] = emb[items[b * L + l] * H + tt];
    }
}

// ---------------- GRU elementwise + final + fp16 splits (padded + compact) ----------------
__global__ void k_gru_elem(const int* __restrict__ items, const int* __restrict__ lens,
                           const float* __restrict__ pos_emb) {
    int i = blockIdx.x * blockDim.x + threadIdx.x;
    int bl = i >> 7, t = i & 127;
    int b = bl / L, l = bl % L;
    const float* g = g_gates + bl * 512;
    float r = 1.f / (1.f + expf(-g[t]));
    float z = 1.f / (1.f + expf(-g[128 + t]));
    float n = tanhf(g[256 + t] + r * g[384 + t]);
    float h0 = g_cat[bl * 384 + 256 + t];
    float hn = n + z * (h0 - n);
    int item = items[bl];
    int len  = lens[b];
    int rev  = (item == 0) ? 0 : (len - 1 - l);
    float fin = fmaxf(g_sg[i], 0.f) + hn + pos_emb[rev * H + t];
    g_final[i] = fin;
    __half fh = __float2half(fin);
    __half fl = __float2half(fin - __half2float(fh));
    g_fh[(b * LP + l) * H + t] = fh;
    g_fl[(b * LP + l) * H + t] = fl;
    g_fch[i] = fh;
    g_fcl[i] = fl;
    if (l == len - 1) g_last[b * H + t] = fin;
}

// ---------------- candidate fp16 convert for tail ----------------
__global__ void k_cvt_cand() {
    int i = blockIdx.x * blockDim.x + threadIdx.x;   // NCP*H
    int n = i >> 7;
    float vT = 0.f, vA = 0.f;
    if (n < NC) { vT = g_cT[i]; vA = g_cA[i]; }
    g_cTh[i] = __float2half(vT);
    g_cAh[i] = __float2half(vA);
}

// ---------------- attention readout -> g_u ----------------
#define ATTN_SMEM ((L * 2 * H + H + 8 * 64 + 3 * H) * 4 + 64 * 4)
__global__ void k_attn(const int* __restrict__ items,
                       const float* __restrict__ ipw, const float* __restrict__ ipb,
                       const float* __restrict__ opw, const float* __restrict__ opb,
                       const float* __restrict__ w3) {
    extern __shared__ float sm[];
    float* kvs = sm;
    float* qs  = kvs + L * 2 * H;
    float* att = qs + H;
    float* ctx = att + 8 * 64;
    float* sg  = ctx + H;
    float* ls  = sg + H;
    int*   its = (int*)(ls + H);

    int b = blockIdx.x, t = threadIdx.x;
    for (int i = t; i < L * 2 * H; i += 256) kvs[i] = g_kv[b * L * 2 * H + i];
    if (t < H) ls[t] = g_last[b * H + t];
    if (t < L) its[t] = items[b * L + t];
    __syncthreads();

    if (t < H) {
        float a = ipb[t];
        const float* w = ipw + t * H;
        #pragma unroll 8
        for (int k = 0; k < H; k++) a += ls[k] * w[k];
        qs[t] = a;
    }
    __syncthreads();
    for (int i = t; i < 8 * L; i += 256) {
        int hd = i / L, l = i % L;
        float a = 0.f;
        #pragma unroll
        for (int d = 0; d < 16; d++) a += qs[hd * 16 + d] * kvs[l * 2 * H + hd * 16 + d];
        att[hd * 64 + l] = (its[l] == 0) ? -INFINITY : a * 0.25f;
    }
    __syncthreads();
    if (t < 8) {
        float m = -INFINITY;
        for (int l = 0; l < L; l++) m = fmaxf(m, att[t * 64 + l]);
        float s = 0.f;
        for (int l = 0; l < L; l++) {
            float e = expf(att[t * 64 + l] - m);
            att[t * 64 + l] = e;
            s += e;
        }
        float inv = 1.f / s;
        for (int l = 0; l < L; l++) att[t * 64 + l] *= inv;
    }
    __syncthreads();
    if (t < H) {
        int hd = t / 16;
        float c = 0.f;
        for (int l = 0; l < L; l++) c += att[hd * 64 + l] * kvs[l * 2 * H + H + t];
        ctx[t] = c;
    }
    __syncthreads();
    if (t < H) {
        float a = opb[t];
        const float* w = opw + t * H;
        #pragma unroll 8
        for (int k = 0; k < H; k++) a += ctx[k] * w[k];
        sg[t] = a;
    }
    __syncthreads();
    if (t < H) {
        float u = 0.f;
        const float* w1 = w3 + t * 3 * H + H;
        const float* w2 = w3 + t * 3 * H + 2 * H;
        #pragma unroll 8
        for (int k = 0; k < H; k++) u += ls[k] * w1[k] + sg[k] * w2[k];
        g_u[b * H + t] = u;
    }
}

// ---------------- tensor-core tail (R10 variant) ----------------
#define T_CT  0
#define T_CA  32768
#define T_F   65536
#define T_ITS 98304
#define TAIL_SMEM (T_ITS + 256)

__global__ void __launch_bounds__(256, 2) k_tail(const int* __restrict__ items,
                                                 float* __restrict__ out) {
    extern __shared__ char smc[];
    uint32_t sb = (uint32_t)__cvta_generic_to_shared(smc);
    int*   its = (int*)(smc + T_ITS);

    int n0 = blockIdx.x * 128;
    int bg = blockIdx.y * 8;
    int t  = threadIdx.x;
    int w  = t >> 5, lane = t & 31;
    int mat = lane >> 3, rin = lane & 7;
    int g = lane >> 2, tg = lane & 3;
    int Rm = 16 * w;

    #pragma unroll
    for (int it = 0; it < 8; it++) {
        int idx = t + 256 * it;
        int r = idx >> 4, c = idx & 15;
        uint4 v = *(const uint4*)&g_cTh[(n0 + r) * H + c * 8];
        *(uint4*)(smc + T_CT + r * 256 + ((c ^ (r & 7)) << 4)) = v;
    }
    #pragma unroll
    for (int it = 0; it < 8; it++) {
        int idx = t + 256 * it;
        int r = idx >> 4, c = idx & 15;
        uint4 v = *(const uint4*)&g_cAh[(n0 + r) * H + c * 8];
        *(uint4*)(smc + T_CA + r * 256 + ((c ^ (r & 7)) << 4)) = v;
    }

    for (int bi = 0; bi < 8; bi++) {
        int b = bg + bi;
        #pragma unroll
        for (int it = 0; it < 8; it++) {
            int idx = t + 256 * it;
            int r = idx >> 5, c = idx & 31;
            const __half* src = (c < 16) ? &g_fh[(b * LP + r) * H + c * 8]
                                         : &g_fl[(b * LP + r) * H + (c - 16) * 8];
            uint4 v = *(const uint4*)src;
            *(uint4*)(smc + T_F + r * 512 + ((c ^ (r & 7)) << 4)) = v;
        }
        if (t < 64) its[t] = (t < L) ? items[b * L + t] : 0;
        __syncthreads();

        float Sacc[8][4] = {}, Gacc[8][4] = {};
        for (int kc = 0; kc < 8; kc++) {
            uint32_t aT[4], aA[4];
            int row_a = Rm + rin + ((mat & 1) << 3);
            int ch_a  = 2 * kc + (mat >> 1);
            ldsm_x4(swz(sb + T_CT, row_a, ch_a, 16), aT[0], aT[1], aT[2], aT[3]);
            ldsm_x4(swz(sb + T_CA, row_a, ch_a, 16), aA[0], aA[1], aA[2], aA[3]);
            int row_b = rin + ((mat >> 1) << 3);
            uint32_t bf[4][4];
            #pragma unroll
            for (int nh = 0; nh < 4; nh++)
                ldsm_x4(swz(sb + T_F, 16 * nh + row_b, 2 * kc + (mat & 1), 32),
                        bf[nh][0], bf[nh][1], bf[nh][2], bf[nh][3]);
            #pragma unroll
            for (int j = 0; j < 8; j++) {
                uint32_t b0 = bf[j >> 1][2 * (j & 1)], b1 = bf[j >> 1][2 * (j & 1) + 1];
                mma_fp16(Sacc[j], aT[0], aT[1], aT[2], aT[3], b0, b1);
                mma_fp16(Gacc[j], aA[0], aA[1], aA[2], aA[3], b0, b1);
            }
            #pragma unroll
            for (int nh = 0; nh < 4; nh++)
                ldsm_x4(swz(sb + T_F, 16 * nh + row_b, 16 + 2 * kc + (mat & 1), 32),
                        bf[nh][0], bf[nh][1], bf[nh][2], bf[nh][3]);
            #pragma unroll
            for (int j = 0; j < 8; j++) {
                uint32_t b0 = bf[j >> 1][2 * (j & 1)], b1 = bf[j >> 1][2 * (j & 1) + 1];
                mma_fp16(Gacc[j], aA[0], aA[1], aA[2], aA[3], b0, b1);
            }
        }

        unsigned mk0 = 0, mk1 = 0;
        #pragma unroll
        for (int j = 0; j < 8; j++) {
            if (its[8 * j + 2 * tg] != 0)     mk0 |= (1u << j);
            if (its[8 * j + 2 * tg + 1] != 0) mk1 |= (1u << j);
        }
        #pragma unroll
        for (int h = 0; h < 2; h++) {
            float m = -INFINITY;
            #pragma unroll
            for (int j = 0; j < 8; j++) {
                if (mk0 & (1u << j)) m = fmaxf(m, Sacc[j][2 * h]);
                if (mk1 & (1u << j)) m = fmaxf(m, Sacc[j][2 * h + 1]);
            }
            m = fmaxf(m, __shfl_xor_sync(0xFFFFFFFF, m, 1));
            m = fmaxf(m, __shfl_xor_sync(0xFFFFFFFF, m, 2));
            float s = 0.f, acc = 0.f;
            #pragma unroll
            for (int j = 0; j < 8; j++) {
                if (mk0 & (1u << j)) {
                    float e = __expf(Sacc[j][2 * h] - m);
                    s += e; acc += e * Gacc[j][2 * h];
                }
                if (mk1 & (1u << j)) {
                    float e = __expf(Sacc[j][2 * h + 1] - m);
                    s += e; acc += e * Gacc[j][2 * h + 1];
                }
            }
            s   += __shfl_xor_sync(0xFFFFFFFF, s, 1);
            s   += __shfl_xor_sync(0xFFFFFFFF, s, 2);
            acc += __shfl_xor_sync(0xFFFFFFFF, acc, 1);
            acc += __shfl_xor_sync(0xFFFFFFFF, acc, 2);
            if (tg == 0) {
                int gn = n0 + Rm + g + 8 * h;
                if (gn < NC) out[b * NC + gn] = acc / s;
            }
        }
        __syncthreads();
    }
}

// ---------------- host launcher ----------------
extern "C" void kernel_launch(void* const* d_in, const int* in_sizes, int n_in,
                              void* d_out, int out_size) {
    const int*   items = (const int*)d_in[0];
    const int*   lens  = (const int*)d_in[1];
    const float* adj   = (const float*)d_in[2];
    const int*   erow  = (const int*)d_in[3];
    const int*   ecol  = (const int*)d_in[4];
    const float* ew    = (const float*)d_in[5];
    const float* emb   = (const float*)d_in[6];
    const float* pos   = (const float*)d_in[7];
    const float* gW    = (const float*)d_in[8];
    const float* gb    = (const float*)d_in[9];
    const float* liW   = (const float*)d_in[10];
    const float* lib   = (const float*)d_in[11];
    const float* loW   = (const float*)d_in[12];
    const float* lob   = (const float*)d_in[13];
    const float* w_ih  = (const float*)d_in[14];
    const float* w_hh  = (const float*)d_in[15];
    const float* b_ih  = (const float*)d_in[16];
    const float* b_hh  = (const float*)d_in[17];
    const float* ipw   = (const float*)d_in[18];
    const float* ipb   = (const float*)d_in[19];
    const float* opw   = (const float*)d_in[20];
    const float* opb   = (const float*)d_in[21];
    const float* wt    = (const float*)d_in[22];
    const float* w3    = (const float*)d_in[23];
    float* out = (float*)d_out;

    static bool s_init = false;
    static cudaStream_t s1, s2, s3;
    static cudaEvent_t evRoot, evCand, evGru, evGE, evUC;
    if (!s_init) {
        cudaStreamCreateWithFlags(&s1, cudaStreamNonBlocking);
        cudaStreamCreateWithFlags(&s2, cudaStreamNonBlocking);
        cudaStreamCreateWithFlags(&s3, cudaStreamNonBlocking);
        cudaEventCreateWithFlags(&evRoot, cudaEventDisableTiming);
        cudaEventCreateWithFlags(&evCand, cudaEventDisableTiming);
        cudaEventCreateWithFlags(&evGru,  cudaEventDisableTiming);
        cudaEventCreateWithFlags(&evGE,   cudaEventDisableTiming);
        cudaEventCreateWithFlags(&evUC,   cudaEventDisableTiming);
        cudaFuncSetAttribute(k_attn, cudaFuncAttributeMaxDynamicSharedMemorySize, ATTN_SMEM);
        cudaFuncSetAttribute(k_tail, cudaFuncAttributeMaxDynamicSharedMemorySize, TAIL_SMEM);
        cudaFuncSetAttribute(k_prop, cudaFuncAttributeMaxDynamicSharedMemorySize, PROP_SMEM);
        cudaFuncSetAttribute(k_gemm16, cudaFuncAttributeMaxDynamicSharedMemorySize, G16_SMEM);
        s_init = true;
    }

    float* p_agg;   cudaGetSymbolAddress((void**)&p_agg,   g_agg);
    int*   p_mark;  cudaGetSymbolAddress((void**)&p_mark,  g_mark);
    float* p_sg;    cudaGetSymbolAddress((void**)&p_sg,    g_sg);
    float* p_ao;    cudaGetSymbolAddress((void**)&p_ao,    g_ao);
    float* p_cat;   cudaGetSymbolAddress((void**)&p_cat,   g_cat);
    float* p_gates; cudaGetSymbolAddress((void**)&p_gates, g_gates);
    float* p_kv;    cudaGetSymbolAddress((void**)&p_kv,    g_kv);
    float* p_u;     cudaGetSymbolAddress((void**)&p_u,     g_u);
    float* p_uc;    cudaGetSymbolAddress((void**)&p_uc,    g_uc);
    float* p_cT;    cudaGetSymbolAddress((void**)&p_cT,    g_cT);
    float* p_cA;    cudaGetSymbolAddress((void**)&p_cA,    g_cA);
    float* p_bc;    cudaGetSymbolAddress((void**)&p_bc,    g_bc);
    float* p_bio;   cudaGetSymbolAddress((void**)&p_bio,   g_bio);
    __half *p_cAh1, *p_cAl1, *p_Ah2, *p_Al2, *p_Ah3, *p_Al3, *p_Ah4, *p_Al4, *p_fch, *p_fcl;
    __half *p_gWh, *p_gWl, *p_kvwh, *p_kvwl, *p_wth, *p_wtl, *p_w3h, *p_w3l;
    __half *p_Wch, *p_Wcl, *p_Wioh, *p_Wiol;
    cudaGetSymbolAddress((void**)&p_cAh1, g_cAh1); cudaGetSymbolAddress((void**)&p_cAl1, g_cAl1);
    cudaGetSymbolAddress((void**)&p_Ah2, g_Ah2);   cudaGetSymbolAddress((void**)&p_Al2, g_Al2);
    cudaGetSymbolAddress((void**)&p_Ah3, g_Ah3);   cudaGetSymbolAddress((void**)&p_Al3, g_Al3);
    cudaGetSymbolAddress((void**)&p_Ah4, g_Ah4);   cudaGetSymbolAddress((void**)&p_Al4, g_Al4);
    cudaGetSymbolAddress((void**)&p_fch, g_fch);   cudaGetSymbolAddress((void**)&p_fcl, g_fcl);
    cudaGetSymbolAddress((void**)&p_gWh, g_gWh);   cudaGetSymbolAddress((void**)&p_gWl, g_gWl);
    cudaGetSymbolAddress((void**)&p_kvwh, g_kvwh); cudaGetSymbolAddress((void**)&p_kvwl, g_kvwl);
    cudaGetSymbolAddress((void**)&p_wth, g_wth);   cudaGetSymbolAddress((void**)&p_wtl, g_wtl);
    cudaGetSymbolAddress((void**)&p_w3h, g_w3h);   cudaGetSymbolAddress((void**)&p_w3l, g_w3l);
    cudaGetSymbolAddress((void**)&p_Wch, g_Wch);   cudaGetSymbolAddress((void**)&p_Wcl, g_Wcl);
    cudaGetSymbolAddress((void**)&p_Wioh, g_Wioh); cudaGetSymbolAddress((void**)&p_Wiol, g_Wiol);

    const int M = B * L;   // 3200

    cudaEventRecord(evRoot, 0);
    cudaStreamWaitEvent(s1, evRoot, 0);
    cudaStreamWaitEvent(s2, evRoot, 0);

    // ---- s1: candidate chain (fp16 GEMMs) ----
    k_cvtA<<<(NC * H + 255) / 256, 256, 0, s1>>>(emb + H, nullptr, p_cAh1, p_cAl1, NC, H);
    k_cvtw1<<<256, 128, 0, s1>>>(wt, w3);
    k_gemm16<<<dim3(2, (NC + 127) / 128), 256, G16_SMEM, s1>>>(
        p_cAh1, p_cAl1, p_wth, p_wtl, (const float*)nullptr, p_cT, NC, H, H);
    k_gemm16<<<dim3(2, (NC + 127) / 128), 256, G16_SMEM, s1>>>(
        p_cAh1, p_cAl1, p_w3h, p_w3l, (const float*)nullptr, p_cA, NC, H, H);
    k_cvt_cand<<<(NCP * H) / 256, 256, 0, s1>>>();
    cudaEventRecord(evCand, s1);

    // ---- s2: GRU chain ----
    k_cvtA<<<(M * H + 255) / 256, 256, 0, s2>>>(emb, items, p_Ah3, p_Al3, M, H);
    k_prep<<<768, 384, 0, s2>>>(liW, lib, loW, lob, w_ih, w_hh, b_ih, b_hh);
    k_gemm16<<<dim3(4, 25), 256, G16_SMEM, s2>>>(
        p_Ah3, p_Al3, p_Wioh, p_Wiol, p_bio, p_ao, M, 256, H);
    k_prop<<<B, 256, PROP_SMEM, s2>>>(adj, items, emb);
    k_cvtA<<<(M * 384 + 255) / 256, 256, 0, s2>>>(p_cat, nullptr, p_Ah2, p_Al2, M, 384);
    k_gemm16<<<dim3(8, 25), 256, G16_SMEM, s2>>>(
        p_Ah2, p_Al2, p_Wch, p_Wcl, p_bc, p_gates, M, 512, 384);
    cudaEventRecord(evGru, s2);

    // ---- s0: edge scatter + sg ----
    k_cvtw0<<<384, 128>>>(gW, ipw + H * H);
    cudaMemsetAsync(p_agg, 0, NI * H * sizeof(float));
    cudaMemsetAsync(p_mark, 0, NI * sizeof(int));
    k_mark<<<(B * L + 255) / 256, 256>>>(items);
    k_edge<<<(E * 32 + 255) / 256, 256>>>(erow, ecol, ew, emb);
    k_cvtA<<<(M * H + 255) / 256, 256>>>(p_agg, items, p_Ah4, p_Al4, M, H);
    k_gemm16<<<dim3(2, 25), 256, G16_SMEM>>>(
        p_Ah4, p_Al4, p_gWh, p_gWl, gb, p_sg, M, H, H);

    cudaStreamWaitEvent(0, evGru, 0);
    k_gru_elem<<<(M * H) / 256, 256>>>(items, lens, pos);
    cudaEventRecord(evGE, 0);

    // ---- s3: attention branch + uc (concurrent with tail) ----
    cudaStreamWaitEvent(s3, evGE, 0);
    k_gemm16<<<dim3(4, 25), 256, G16_SMEM, s3>>>(
        p_fch, p_fcl, p_kvwh, p_kvwl, ipb + H, p_kv, M, 256, H);
    k_attn<<<B, 256, ATTN_SMEM, s3>>>(items, ipw, ipb, opw, opb, w3);
    k_gemm<<<dim3((NC + 63) / 64, 1), 256, 0, s3>>>(p_u, emb + H, p_uc, B, NC, H);
    cudaEventRecord(evUC, s3);

    // ---- s0: tail, then add ----
    cudaStreamWaitEvent(0, evCand, 0);
    k_tail<<<dim3(NCP / 128, B / 8), 256, TAIL_SMEM>>>(items, out);

    cudaStreamWaitEvent(0, evUC, 0);
    k_add<<<(B * NC + 255) / 256, 256>>>(out);
}

// round 13
// speedup vs baseline: 1.0909x; 1.0130x over previous
#include <cuda_runtime.h>
#include <cuda_bf16.h>
#include <cuda_fp16.h>
#include <math.h>
#include <stdint.h>

#define NI 10000
#define H  128
#define L  50
#define B  64
#define E  160000
#define NC 9999
#define NCP 10112     // NC padded to 128*79
#define LP 64         // L padded for MMA

// ---------------- persistent device scratch ----------------
__device__ float g_agg[NI * H];
__device__ int   g_mark[NI];
__device__ float g_sg [B * L * H];        // pre-relu
__device__ float g_ao [B * L * 256];      // [ain|aout]
__device__ float g_gates[B * L * 512];    // [r_sum | z_sum | i_n | h_n]
__device__ float g_kv [B * L * 2 * H];
__device__ float g_last[B * H];
__device__ float g_u  [B * H];
__device__ float g_uc [B * NC];
__device__ float g_cTA[NC * 256];         // [cT | cA]
__device__ float g_bc [512];
__device__ float g_bio[256];
// fp16 split operands
__device__ __half g_Ah2[B * L * 384], g_Al2[B * L * 384]; // [inp|h0] for gates GEMM
__device__ __half g_fch[B * L * H], g_fcl[B * L * H];     // final compact
// fp16 split weights
__device__ __half g_gWh[H * H],    g_gWl[H * H];
__device__ __half g_kvwh[256 * H], g_kvwl[256 * H];
__device__ __half g_wcth[256 * H], g_wctl[256 * H];       // [wt | w3^T]
__device__ __half g_Wch[512 * 384], g_Wcl[512 * 384];
__device__ __half g_Wioh[256 * H], g_Wiol[256 * H];
// tail operands
__device__ __half g_fh [B * LP * H];      // zero-padded rows >= L (never written there)
__device__ __half g_fl [B * LP * H];
__device__ __half g_cTh[NCP * H];
__device__ __half g_cAh[NCP * H];

// ---------------- mma helpers ----------------
__device__ __forceinline__ void ldsm_x4(uint32_t addr, uint32_t& r0, uint32_t& r1,
                                        uint32_t& r2, uint32_t& r3) {
    asm volatile("ldmatrix.sync.aligned.m8n8.x4.shared.b16 {%0,%1,%2,%3}, [%4];"
                 : "=r"(r0), "=r"(r1), "=r"(r2), "=r"(r3) : "r"(addr));
}
__device__ __forceinline__ void mma_fp16(float* d, uint32_t a0, uint32_t a1,
                                         uint32_t a2, uint32_t a3,
                                         uint32_t b0, uint32_t b1) {
    asm volatile(
        "mma.sync.aligned.m16n8k16.row.col.f32.f16.f16.f32 "
        "{%0,%1,%2,%3}, {%4,%5,%6,%7}, {%8,%9}, {%0,%1,%2,%3};"
        : "+f"(d[0]), "+f"(d[1]), "+f"(d[2]), "+f"(d[3])
        : "r"(a0), "r"(a1), "r"(a2), "r"(a3), "r"(b0), "r"(b1));
}
__device__ __forceinline__ uint32_t swz(uint32_t base, int row, int ch, int rs_ch) {
    return base + (uint32_t)(row * rs_ch * 16 + (((ch) ^ (row & 7)) << 4));
}

// ---------------- mark session items ----------------
__global__ void k_mark(const int* __restrict__ items) {
    int i = blockIdx.x * blockDim.x + threadIdx.x;
    if (i < B * L) g_mark[items[i]] = 1;
}

// ---------------- edge scatter ----------------
__global__ void k_edge(const int* __restrict__ row, const int* __restrict__ col,
                       const float* __restrict__ w, const float* __restrict__ emb) {
    int i = blockIdx.x * blockDim.x + threadIdx.x;
    int e = i >> 5;
    int q = i & 31;
    if (e < E) {
        int r = row[e];
        if (g_mark[r]) {
            float ww = w[e];
            int c = col[e];
            float4 v = ((const float4*)(emb + c * H))[q];
            v.x *= ww; v.y *= ww; v.z *= ww; v.w *= ww;
            float* dst = &g_agg[r * H + q * 4];
            asm volatile("red.global.add.v4.f32 [%0], {%1, %2, %3, %4};"
                         :: "l"(dst), "f"(v.x), "f"(v.y), "f"(v.z), "f"(v.w)
                         : "memory");
        }
    }
}

// ---------------- s1 weight prep: wcat = [wt | w3^T] fp16 h/l ----------------
__global__ void k_prep1(const float* __restrict__ wt, const float* __restrict__ w3) {
    int n = blockIdx.x, k = threadIdx.x;   // 256 x 128
    float v = (n < 128) ? wt[n * H + k] : w3[k * 384 + (n - 128)];
    __half h = __float2half(v);
    g_wcth[n * H + k] = h;
    g_wctl[n * H + k] = __float2half(v - __half2float(h));
}

// ---------------- s2 weight prep: Wc, Wio, gW, kvw + biases ----------------
__global__ void k_prep2(const float* __restrict__ liW, const float* __restrict__ lib,
                        const float* __restrict__ loW, const float* __restrict__ lob,
                        const float* __restrict__ w_ih, const float* __restrict__ w_hh,
                        const float* __restrict__ b_ih, const float* __restrict__ b_hh,
                        const float* __restrict__ gW, const float* __restrict__ kvw) {
    int n = blockIdx.x, k = threadIdx.x;   // 1152 x 384
    if (n < 512) {
        int j = n & 127;
        int sec = n >> 7;
        float v;
        if (sec <= 1) {
            int row = sec * 128 + j;
            v = (k < 256) ? w_ih[row * 256 + k] : w_hh[row * 128 + (k - 256)];
        } else if (sec == 2) {
            v = (k < 256) ? w_ih[(256 + j) * 256 + k] : 0.f;
        } else {
            v = (k < 256) ? 0.f : w_hh[(256 + j) * 128 + (k - 256)];
        }
        __half h = __float2half(v);
        g_Wch[n * 384 + k] = h;
        g_Wcl[n * 384 + k] = __float2half(v - __half2float(h));
        if (k == 0) {
            float bb;
            if (sec == 0)      bb = b_ih[j] + b_hh[j];
            else if (sec == 1) bb = b_ih[128 + j] + b_hh[128 + j];
            else if (sec == 2) bb = b_ih[256 + j];
            else               bb = b_hh[256 + j];
            g_bc[n] = bb;
        }
    } else if (n < 768) {
        int m = n - 512;
        if (k < 128) {
            float v = (m < 128) ? liW[m * 128 + k] : loW[(m - 128) * 128 + k];
            __half h = __float2half(v);
            g_Wioh[m * 128 + k] = h;
            g_Wiol[m * 128 + k] = __float2half(v - __half2float(h));
            if (k == 0) g_bio[m] = (m < 128) ? lib[m] : lob[m - 128];
        }
    } else if (n < 896) {
        int m = n - 768;
        if (k < 128) {
            float v = gW[m * H + k];
            __half h = __float2half(v);
            g_gWh[m * H + k] = h;
            g_gWl[m * H + k] = __float2half(v - __half2float(h));
        }
    } else {
        int m = n - 896;
        if (k < 128) {
            float v = kvw[m * H + k];
            __half h = __float2half(v);
            g_kvwh[m * H + k] = h;
            g_kvwl[m * H + k] = __float2half(v - __half2float(h));
        }
    }
}

// ---------------- tensor-core GEMM: C = A@(Bh+Bl)^T + bias (3-term compensated) ----------------
// a32: A is fp32 (split during staging), else A = (Ah, Al) fp16 pair. aidx: row gather.
#define G16_SMEM 49152
__global__ void __launch_bounds__(256) k_gemm16(
    const void* __restrict__ A, const __half* __restrict__ Al_,
    const __half* __restrict__ Bh, const __half* __restrict__ Bl,
    const float* __restrict__ bias, float* __restrict__ C,
    int M, int N, int K, int a32, const int* __restrict__ aidx) {
    extern __shared__ char smc[];
    uint32_t sb = (uint32_t)__cvta_generic_to_shared(smc);
    const int SA_H = 0, SA_L = 16384, SB_H = 32768, SB_L = 40960;
    int t = threadIdx.x;
    int w = t >> 5, lane = t & 31;
    int mat = lane >> 3, rin = lane & 7;
    int g = lane >> 2, tg = lane & 3;
    int Rm = 16 * w;
    int m0 = blockIdx.y * 128, n0 = blockIdx.x * 64;
    int row_a = Rm + rin + ((mat & 1) << 3);
    int row_b = rin + ((mat >> 1) << 3);

    float acc[8][4] = {};
    for (int k0 = 0; k0 < K; k0 += 64) {
        #pragma unroll
        for (int it = 0; it < 4; it++) {
            int idx = t + 256 * it;      // 1024: 128 rows x 8 chunks
            int r = idx >> 3, c = idx & 7;
            int gm = m0 + r;
            uint4 vh = make_uint4(0, 0, 0, 0), vl = vh;
            if (gm < M) {
                int am = aidx ? aidx[gm] : gm;
                if (a32) {
                    const float* Af = (const float*)A + (size_t)am * K + k0 + c * 8;
                    float4 v0 = *(const float4*)Af;
                    float4 v1 = *(const float4*)(Af + 4);
                    float vs[8] = { v0.x, v0.y, v0.z, v0.w, v1.x, v1.y, v1.z, v1.w };
                    __half hh[8], ll[8];
                    #pragma unroll
                    for (int q = 0; q < 8; q++) {
                        hh[q] = __float2half(vs[q]);
                        ll[q] = __float2half(vs[q] - __half2float(hh[q]));
                    }
                    vh = *(uint4*)hh;
                    vl = *(uint4*)ll;
                } else {
                    vh = *(const uint4*)&((const __half*)A)[(size_t)am * K + k0 + c * 8];
                    vl = *(const uint4*)&Al_[(size_t)am * K + k0 + c * 8];
                }
            }
            uint32_t off = (uint32_t)(r * 128 + ((c ^ (r & 7)) << 4));
            *(uint4*)(smc + SA_H + off) = vh;
            *(uint4*)(smc + SA_L + off) = vl;
        }
        #pragma unroll
        for (int it = 0; it < 2; it++) {
            int idx = t + 256 * it;      // 512: 64 rows x 8 chunks
            int r = idx >> 3, c = idx & 7;
            int gn = n0 + r;
            uint4 vh = make_uint4(0, 0, 0, 0), vl = vh;
            if (gn < N) {
                vh = *(const uint4*)&Bh[gn * K + k0 + c * 8];
                vl = *(const uint4*)&Bl[gn * K + k0 + c * 8];
            }
            uint32_t off = (uint32_t)(r * 128 + ((c ^ (r & 7)) << 4));
            *(uint4*)(smc + SB_H + off) = vh;
            *(uint4*)(smc + SB_L + off) = vl;
        }
        __syncthreads();
        #pragma unroll
        for (int k16 = 0; k16 < 4; k16++) {
            uint32_t aH[4], aL[4];
            int ca = 2 * k16 + (mat >> 1);
            ldsm_x4(swz(sb + SA_H, row_a, ca, 8), aH[0], aH[1], aH[2], aH[3]);
            ldsm_x4(swz(sb + SA_L, row_a, ca, 8), aL[0], aL[1], aL[2], aL[3]);
            int cb = 2 * k16 + (mat & 1);
            uint32_t bH[4][4], bL[4][4];
            #pragma unroll
            for (int nh = 0; nh < 4; nh++) {
                ldsm_x4(swz(sb + SB_H, 16 * nh + row_b, cb, 8),
                        bH[nh][0], bH[nh][1], bH[nh][2], bH[nh][3]);
                ldsm_x4(swz(sb + SB_L, 16 * nh + row_b, cb, 8),
                        bL[nh][0], bL[nh][1], bL[nh][2], bL[nh][3]);
            }
            #pragma unroll
            for (int j = 0; j < 8; j++) {
                uint32_t h0 = bH[j >> 1][2 * (j & 1)], h1 = bH[j >> 1][2 * (j & 1) + 1];
                uint32_t l0 = bL[j >> 1][2 * (j & 1)], l1 = bL[j >> 1][2 * (j & 1) + 1];
                mma_fp16(acc[j], aH[0], aH[1], aH[2], aH[3], h0, h1);
                mma_fp16(acc[j], aL[0], aL[1], aL[2], aL[3], h0, h1);
                mma_fp16(acc[j], aH[0], aH[1], aH[2], aH[3], l0, l1);
            }
        }
        __syncthreads();
    }
    #pragma unroll
    for (int j = 0; j < 8; j++) {
        int gn = n0 + 8 * j + 2 * tg;
        if (gn < N) {
            float b0 = bias ? bias[gn] : 0.f;
            float b1 = bias ? bias[gn + 1] : 0.f;
            int gm0 = m0 + Rm + g;
            if (gm0 < M)
                *(float2*)&C[(size_t)gm0 * N + gn] = make_float2(acc[j][0] + b0, acc[j][1] + b1);
            if (gm0 + 8 < M)
                *(float2*)&C[(size_t)(gm0 + 8) * N + gn] = make_float2(acc[j][2] + b0, acc[j][3] + b1);
        }
    }
}

// ---------------- scalar GEMM (uc only) ----------------
__global__ void __launch_bounds__(256) k_gemm(const float* __restrict__ A,
                                              const float* __restrict__ Bw,
                                              float* __restrict__ C,
                                              int M, int N, int K) {
    __shared__ float As[64][33];
    __shared__ float Bs[64][33];
    int m0 = blockIdx.y * 64, n0 = blockIdx.x * 64;
    int tid = threadIdx.x;
    int tx = tid & 15, ty = tid >> 4;
    float acc[4][4] = {};
    for (int k0 = 0; k0 < K; k0 += 32) {
        #pragma unroll
        for (int i = 0; i < 2; i++) {
            int f = tid + 256 * i;
            int m = f >> 3, k4 = f & 7;
            int gm = m0 + m;
            float4 v = make_float4(0.f, 0.f, 0.f, 0.f);
            if (gm < M) v = *(const float4*)&A[gm * K + k0 + k4 * 4];
            As[m][k4 * 4 + 0] = v.x; As[m][k4 * 4 + 1] = v.y;
            As[m][k4 * 4 + 2] = v.z; As[m][k4 * 4 + 3] = v.w;
        }
        #pragma unroll
        for (int i = 0; i < 2; i++) {
            int f = tid + 256 * i;
            int n = f >> 3, k4 = f & 7;
            int gn = n0 + n;
            float4 v = make_float4(0.f, 0.f, 0.f, 0.f);
            if (gn < N) v = *(const float4*)&Bw[gn * K + k0 + k4 * 4];
            Bs[n][k4 * 4 + 0] = v.x; Bs[n][k4 * 4 + 1] = v.y;
            Bs[n][k4 * 4 + 2] = v.z; Bs[n][k4 * 4 + 3] = v.w;
        }
        __syncthreads();
        #pragma unroll
        for (int k = 0; k < 32; k++) {
            float a[4], b[4];
            #pragma unroll
            for (int r = 0; r < 4; r++) a[r] = As[ty * 4 + r][k];
            #pragma unroll
            for (int c = 0; c < 4; c++) b[c] = Bs[tx * 4 + c][k];
            #pragma unroll
            for (int r = 0; r < 4; r++)
                #pragma unroll
                for (int c = 0; c < 4; c++)
                    acc[r][c] += a[r] * b[c];
        }
        __syncthreads();
    }
    #pragma unroll
    for (int r = 0; r < 4; r++) {
        int gm = m0 + ty * 4 + r;
        if (gm < M) {
            #pragma unroll
            for (int c = 0; c < 4; c++) {
                int gn = n0 + tx * 4 + c;
                if (gn < N) C[gm * N + gn] = acc[r][c];
            }
        }
    }
}

// ---------------- final add ----------------
__global__ void k_add(float* __restrict__ out) {
    int i = blockIdx.x * blockDim.x + threadIdx.x;
    if (i < B * NC) out[i] += g_uc[i];
}

// ---------------- prop: inp = adj @ ao; writes fp16 [inp|h0] operand ----------------
#define PROP_SMEM ((L * L + L * 256) * 4)
__global__ void k_prop(const float* __restrict__ adj, const int* __restrict__ items,
                       const float* __restrict__ emb) {
    extern __shared__ float psm[];
    float* sA  = psm;
    float* sin = psm + L * L;
    int b = blockIdx.x, t = threadIdx.x;
    for (int i = t; i < L * L; i += 256) sA[i] = adj[b * L * L + i];
    for (int k = 0; k < L; k++) sin[k * 256 + t] = g_ao[(b * L + k) * 256 + t];
    __syncthreads();
    for (int l = 0; l < L; l++) {
        float acc = 0.f;
        #pragma unroll 10
        for (int k = 0; k < L; k++)
            acc += sA[l * L + k] * sin[k * 256 + t];
        __half h = __float2half(acc);
        g_Ah2[(b * L + l) * 384 + t] = h;
        g_Al2[(b * L + l) * 384 + t] = __float2half(acc - __half2float(h));
    }
    for (int i = t; i < L * H; i += 256) {
        int l = i >> 7, tt = i & 127;
        float v = emb[items[b * L + l] * H + tt];
        __half h = __float2half(v);
        g_Ah2[(b * L + l) * 384 + 256 + tt] = h;
        g_Al2[(b * L + l) * 384 + 256 + tt] = __float2half(v - __half2float(h));
    }
}

// ---------------- GRU elementwise + final fp16 splits ----------------
__global__ void k_gru_elem(const int* __restrict__ items, const int* __restrict__ lens,
                           const float* __restrict__ pos_emb) {
    int i = blockIdx.x * blockDim.x + threadIdx.x;
    int bl = i >> 7, t = i & 127;
    int b = bl / L, l = bl % L;
    const float* g = g_gates + bl * 512;
    float r = 1.f / (1.f + expf(-g[t]));
    float z = 1.f / (1.f + expf(-g[128 + t]));
    float n = tanhf(g[256 + t] + r * g[384 + t]);
    float h0 = __half2float(g_Ah2[bl * 384 + 256 + t]) + __half2float(g_Al2[bl * 384 + 256 + t]);
    float hn = n + z * (h0 - n);
    int item = items[bl];
    int len  = lens[b];
    int rev  = (item == 0) ? 0 : (len - 1 - l);
    float fin = fmaxf(g_sg[i], 0.f) + hn + pos_emb[rev * H + t];
    __half fh = __float2half(fin);
    __half fl = __float2half(fin - __half2float(fh));
    g_fh[(b * LP + l) * H + t] = fh;
    g_fl[(b * LP + l) * H + t] = fl;
    g_fch[i] = fh;
    g_fcl[i] = fl;
    if (l == len - 1) g_last[b * H + t] = fin;
}

// ---------------- candidate fp16 convert for tail (from combined cTA) ----------------
__global__ void k_cvt_cand() {
    int i = blockIdx.x * blockDim.x + threadIdx.x;   // NCP*H
    int n = i >> 7, k = i & 127;
    float vT = 0.f, vA = 0.f;
    if (n < NC) { vT = g_cTA[n * 256 + k]; vA = g_cTA[n * 256 + 128 + k]; }
    g_cTh[i] = __float2half(vT);
    g_cAh[i] = __float2half(vA);
}

// ---------------- attention readout -> g_u ----------------
#define ATTN_SMEM ((L * 2 * H + H + 8 * 64 + 3 * H) * 4 + 64 * 4)
__global__ void k_attn(const int* __restrict__ items,
                       const float* __restrict__ ipw, const float* __restrict__ ipb,
                       const float* __restrict__ opw, const float* __restrict__ opb,
                       const float* __restrict__ w3) {
    extern __shared__ float sm[];
    float* kvs = sm;
    float* qs  = kvs + L * 2 * H;
    float* att = qs + H;
    float* ctx = att + 8 * 64;
    float* sg  = ctx + H;
    float* ls  = sg + H;
    int*   its = (int*)(ls + H);

    int b = blockIdx.x, t = threadIdx.x;
    for (int i = t; i < L * 2 * H; i += 256) kvs[i] = g_kv[b * L * 2 * H + i];
    if (t < H) ls[t] = g_last[b * H + t];
    if (t < L) its[t] = items[b * L + t];
    __syncthreads();

    if (t < H) {
        float a = ipb[t];
        const float* w = ipw + t * H;
        #pragma unroll 8
        for (int k = 0; k < H; k++) a += ls[k] * w[k];
        qs[t] = a;
    }
    __syncthreads();
    for (int i = t; i < 8 * L; i += 256) {
        int hd = i / L, l = i % L;
        float a = 0.f;
        #pragma unroll
        for (int d = 0; d < 16; d++) a += qs[hd * 16 + d] * kvs[l * 2 * H + hd * 16 + d];
        att[hd * 64 + l] = (its[l] == 0) ? -INFINITY : a * 0.25f;
    }
    __syncthreads();
    if (t < 8) {
        float m = -INFINITY;
        for (int l = 0; l < L; l++) m = fmaxf(m, att[t * 64 + l]);
        float s = 0.f;
        for (int l = 0; l < L; l++) {
            float e = expf(att[t * 64 + l] - m);
            att[t * 64 + l] = e;
            s += e;
        }
        float inv = 1.f / s;
        for (int l = 0; l < L; l++) att[t * 64 + l] *= inv;
    }
    __syncthreads();
    if (t < H) {
        int hd = t / 16;
        float c = 0.f;
        for (int l = 0; l < L; l++) c += att[hd * 64 + l] * kvs[l * 2 * H + H + t];
        ctx[t] = c;
    }
    __syncthreads();
    if (t < H) {
        float a = opb[t];
        const float* w = opw + t * H;
        #pragma unroll 8
        for (int k = 0; k < H; k++) a += ctx[k] * w[k];
        sg[t] = a;
    }
    __syncthreads();
    if (t < H) {
        float u = 0.f;
        const float* w1 = w3 + t * 3 * H + H;
        const float* w2 = w3 + t * 3 * H + 2 * H;
        #pragma unroll 8
        for (int k = 0; k < H; k++) u += ls[k] * w1[k] + sg[k] * w2[k];
        g_u[b * H + t] = u;
    }
}

// ---------------- tensor-core tail ----------------
#define T_CT  0
#define T_CA  32768
#define T_F   65536
#define T_ITS 98304
#define TAIL_SMEM (T_ITS + 256)

__global__ void __launch_bounds__(256, 2) k_tail(const int* __restrict__ items,
                                                 float* __restrict__ out) {
    extern __shared__ char smc[];
    uint32_t sb = (uint32_t)__cvta_generic_to_shared(smc);
    int*   its = (int*)(smc + T_ITS);

    int n0 = blockIdx.x * 128;
    int bg = blockIdx.y * 8;
    int t  = threadIdx.x;
    int w  = t >> 5, lane = t & 31;
    int mat = lane >> 3, rin = lane & 7;
    int g = lane >> 2, tg = lane & 3;
    int Rm = 16 * w;

    #pragma unroll
    for (int it = 0; it < 8; it++) {
        int idx = t + 256 * it;
        int r = idx >> 4, c = idx & 15;
        uint4 v = *(const uint4*)&g_cTh[(n0 + r) * H + c * 8];
        *(uint4*)(smc + T_CT + r * 256 + ((c ^ (r & 7)) << 4)) = v;
    }
    #pragma unroll
    for (int it = 0; it < 8; it++) {
        int idx = t + 256 * it;
        int r = idx >> 4, c = idx & 15;
        uint4 v = *(const uint4*)&g_cAh[(n0 + r) * H + c * 8];
        *(uint4*)(smc + T_CA + r * 256 + ((c ^ (r & 7)) << 4)) = v;
    }

    for (int bi = 0; bi < 8; bi++) {
        int b = bg + bi;
        #pragma unroll
        for (int it = 0; it < 8; it++) {
            int idx = t + 256 * it;
            int r = idx >> 5, c = idx & 31;
            const __half* src = (c < 16) ? &g_fh[(b * LP + r) * H + c * 8]
                                         : &g_fl[(b * LP + r) * H + (c - 16) * 8];
            uint4 v = *(const uint4*)src;
            *(uint4*)(smc + T_F + r * 512 + ((c ^ (r & 7)) << 4)) = v;
        }
        if (t < 64) its[t] = (t < L) ? items[b * L + t] : 0;
        __syncthreads();

        float Sacc[8][4] = {}, Gacc[8][4] = {};
        for (int kc = 0; kc < 8; kc++) {
            uint32_t aT[4], aA[4];
            int row_a = Rm + rin + ((mat & 1) << 3);
            int ch_a  = 2 * kc + (mat >> 1);
            ldsm_x4(swz(sb + T_CT, row_a, ch_a, 16), aT[0], aT[1], aT[2], aT[3]);
            ldsm_x4(swz(sb + T_CA, row_a, ch_a, 16), aA[0], aA[1], aA[2], aA[3]);
            int row_b = rin + ((mat >> 1) << 3);
            uint32_t bf[4][4];
            #pragma unroll
            for (int nh = 0; nh < 4; nh++)
                ldsm_x4(swz(sb + T_F, 16 * nh + row_b, 2 * kc + (mat & 1), 32),
                        bf[nh][0], bf[nh][1], bf[nh][2], bf[nh][3]);
            #pragma unroll
            for (int j = 0; j < 8; j++) {
                uint32_t b0 = bf[j >> 1][2 * (j & 1)], b1 = bf[j >> 1][2 * (j & 1) + 1];
                mma_fp16(Sacc[j], aT[0], aT[1], aT[2], aT[3], b0, b1);
                mma_fp16(Gacc[j], aA[0], aA[1], aA[2], aA[3], b0, b1);
            }
            #pragma unroll
            for (int nh = 0; nh < 4; nh++)
                ldsm_x4(swz(sb + T_F, 16 * nh + row_b, 16 + 2 * kc + (mat & 1), 32),
                        bf[nh][0], bf[nh][1], bf[nh][2], bf[nh][3]);
            #pragma unroll
            for (int j = 0; j < 8; j++) {
                uint32_t b0 = bf[j >> 1][2 * (j & 1)], b1 = bf[j >> 1][2 * (j & 1) + 1];
                mma_fp16(Gacc[j], aA[0], aA[1], aA[2], aA[3], b0, b1);
            }
        }

        unsigned mk0 = 0, mk1 = 0;
        #pragma unroll
        for (int j = 0; j < 8; j++) {
            if (its[8 * j + 2 * tg] != 0)     mk0 |= (1u << j);
            if (its[8 * j + 2 * tg + 1] != 0) mk1 |= (1u << j);
        }
        #pragma unroll
        for (int h = 0; h < 2; h++) {
            float m = -INFINITY;
            #pragma unroll
            for (int j = 0; j < 8; j++) {
                if (mk0 & (1u << j)) m = fmaxf(m, Sacc[j][2 * h]);
                if (mk1 & (1u << j)) m = fmaxf(m, Sacc[j][2 * h + 1]);
            }
            m = fmaxf(m, __shfl_xor_sync(0xFFFFFFFF, m, 1));
            m = fmaxf(m, __shfl_xor_sync(0xFFFFFFFF, m, 2));
            float s = 0.f, acc = 0.f;
            #pragma unroll
            for (int j = 0; j < 8; j++) {
                if (mk0 & (1u << j)) {
                    float e = __expf(Sacc[j][2 * h] - m);
                    s += e; acc += e * Gacc[j][2 * h];
                }
                if (mk1 & (1u << j)) {
                    float e = __expf(Sacc[j][2 * h + 1] - m);
                    s += e; acc += e * Gacc[j][2 * h + 1];
                }
            }
            s   += __shfl_xor_sync(0xFFFFFFFF, s, 1);
            s   += __shfl_xor_sync(0xFFFFFFFF, s, 2);
            acc += __shfl_xor_sync(0xFFFFFFFF, acc, 1);
            acc += __shfl_xor_sync(0xFFFFFFFF, acc, 2);
            if (tg == 0) {
                int gn = n0 + Rm + g + 8 * h;
                if (gn < NC) out[b * NC + gn] = acc / s;
            }
        }
        __syncthreads();
    }
}

// ---------------- host launcher ----------------
extern "C" void kernel_launch(void* const* d_in, const int* in_sizes, int n_in,
                              void* d_out, int out_size) {
    const int*   items = (const int*)d_in[0];
    const int*   lens  = (const int*)d_in[1];
    const float* adj   = (const float*)d_in[2];
    const int*   erow  = (const int*)d_in[3];
    const int*   ecol  = (const int*)d_in[4];
    const float* ew    = (const float*)d_in[5];
    const float* emb   = (const float*)d_in[6];
    const float* pos   = (const float*)d_in[7];
    const float* gW    = (const float*)d_in[8];
    const float* gb    = (const float*)d_in[9];
    const float* liW   = (const float*)d_in[10];
    const float* lib   = (const float*)d_in[11];
    const float* loW   = (const float*)d_in[12];
    const float* lob   = (const float*)d_in[13];
    const float* w_ih  = (const float*)d_in[14];
    const float* w_hh  = (const float*)d_in[15];
    const float* b_ih  = (const float*)d_in[16];
    const float* b_hh  = (const float*)d_in[17];
    const float* ipw   = (const float*)d_in[18];
    const float* ipb   = (const float*)d_in[19];
    const float* opw   = (const float*)d_in[20];
    const float* opb   = (const float*)d_in[21];
    const float* wt    = (const float*)d_in[22];
    const float* w3    = (const float*)d_in[23];
    float* out = (float*)d_out;

    static bool s_init = false;
    static cudaStream_t s1, s2, s3;
    static cudaEvent_t evRoot, evCand, evGru, evGE, evUC, evPrep;
    if (!s_init) {
        cudaStreamCreateWithFlags(&s1, cudaStreamNonBlocking);
        cudaStreamCreateWithFlags(&s2, cudaStreamNonBlocking);
        cudaStreamCreateWithFlags(&s3, cudaStreamNonBlocking);
        cudaEventCreateWithFlags(&evRoot, cudaEventDisableTiming);
        cudaEventCreateWithFlags(&evCand, cudaEventDisableTiming);
        cudaEventCreateWithFlags(&evGru,  cudaEventDisableTiming);
        cudaEventCreateWithFlags(&evGE,   cudaEventDisableTiming);
        cudaEventCreateWithFlags(&evUC,   cudaEventDisableTiming);
        cudaEventCreateWithFlags(&evPrep, cudaEventDisableTiming);
        cudaFuncSetAttribute(k_attn, cudaFuncAttributeMaxDynamicSharedMemorySize, ATTN_SMEM);
        cudaFuncSetAttribute(k_tail, cudaFuncAttributeMaxDynamicSharedMemorySize, TAIL_SMEM);
        cudaFuncSetAttribute(k_prop, cudaFuncAttributeMaxDynamicSharedMemorySize, PROP_SMEM);
        cudaFuncSetAttribute(k_gemm16, cudaFuncAttributeMaxDynamicSharedMemorySize, G16_SMEM);
        s_init = true;
    }

    float* p_agg;   cudaGetSymbolAddress((void**)&p_agg,   g_agg);
    int*   p_mark;  cudaGetSymbolAddress((void**)&p_mark,  g_mark);
    float* p_sg;    cudaGetSymbolAddress((void**)&p_sg,    g_sg);
    float* p_ao;    cudaGetSymbolAddress((void**)&p_ao,    g_ao);
    float* p_gates; cudaGetSymbolAddress((void**)&p_gates, g_gates);
    float* p_kv;    cudaGetSymbolAddress((void**)&p_kv,    g_kv);
    float* p_u;     cudaGetSymbolAddress((void**)&p_u,     g_u);
    float* p_uc;    cudaGetSymbolAddress((void**)&p_uc,    g_uc);
    float* p_cTA;   cudaGetSymbolAddress((void**)&p_cTA,   g_cTA);
    float* p_bc;    cudaGetSymbolAddress((void**)&p_bc,    g_bc);
    float* p_bio;   cudaGetSymbolAddress((void**)&p_bio,   g_bio);
    __half *p_Ah2, *p_Al2, *p_fch, *p_fcl;
    __half *p_gWh, *p_gWl, *p_kvwh, *p_kvwl, *p_wcth, *p_wctl;
    __half *p_Wch, *p_Wcl, *p_Wioh, *p_Wiol;
    cudaGetSymbolAddress((void**)&p_Ah2, g_Ah2);   cudaGetSymbolAddress((void**)&p_Al2, g_Al2);
    cudaGetSymbolAddress((void**)&p_fch, g_fch);   cudaGetSymbolAddress((void**)&p_fcl, g_fcl);
    cudaGetSymbolAddress((void**)&p_gWh, g_gWh);   cudaGetSymbolAddress((void**)&p_gWl, g_gWl);
    cudaGetSymbolAddress((void**)&p_kvwh, g_kvwh); cudaGetSymbolAddress((void**)&p_kvwl, g_kvwl);
    cudaGetSymbolAddress((void**)&p_wcth, g_wcth); cudaGetSymbolAddress((void**)&p_wctl, g_wctl);
    cudaGetSymbolAddress((void**)&p_Wch, g_Wch);   cudaGetSymbolAddress((void**)&p_Wcl, g_Wcl);
    cudaGetSymbolAddress((void**)&p_Wioh, g_Wioh); cudaGetSymbolAddress((void**)&p_Wiol, g_Wiol);

    const int M = B * L;   // 3200

    cudaEventRecord(evRoot, 0);
    cudaStreamWaitEvent(s1, evRoot, 0);
    cudaStreamWaitEvent(s2, evRoot, 0);

    // ---- s1: candidate chain (one combined GEMM, f32 A) ----
    k_prep1<<<256, 128, 0, s1>>>(wt, w3);
    k_gemm16<<<dim3(4, (NC + 127) / 128), 256, G16_SMEM, s1>>>(
        emb + H, nullptr, p_wcth, p_wctl, (const float*)nullptr, p_cTA,
        NC, 256, H, 1, nullptr);
    k_cvt_cand<<<(NCP * H) / 256, 256, 0, s1>>>();
    cudaEventRecord(evCand, s1);

    // ---- s2: GRU chain ----
    k_prep2<<<1152, 384, 0, s2>>>(liW, lib, loW, lob, w_ih, w_hh, b_ih, b_hh,
                                  gW, ipw + H * H);
    cudaEventRecord(evPrep, s2);
    k_gemm16<<<dim3(4, 25), 256, G16_SMEM, s2>>>(
        emb, nullptr, p_Wioh, p_Wiol, p_bio, p_ao, M, 256, H, 1, items);
    k_prop<<<B, 256, PROP_SMEM, s2>>>(adj, items, emb);
    k_gemm16<<<dim3(8, 25), 256, G16_SMEM, s2>>>(
        p_Ah2, p_Al2, p_Wch, p_Wcl, p_bc, p_gates, M, 512, 384, 0, nullptr);
    cudaEventRecord(evGru, s2);

    // ---- s0: edge scatter + sg ----
    cudaMemsetAsync(p_agg, 0, NI * H * sizeof(float));
    cudaMemsetAsync(p_mark, 0, NI * sizeof(int));
    k_mark<<<(B * L + 255) / 256, 256>>>(items);
    k_edge<<<(E * 32 + 255) / 256, 256>>>(erow, ecol, ew, emb);
    cudaStreamWaitEvent(0, evPrep, 0);
    k_gemm16<<<dim3(2, 25), 256, G16_SMEM>>>(
        p_agg, nullptr, p_gWh, p_gWl, gb, p_sg, M, H, H, 1, items);

    cudaStreamWaitEvent(0, evGru, 0);
    k_gru_elem<<<(M * H) / 256, 256>>>(items, lens, pos);
    cudaEventRecord(evGE, 0);

    // ---- s3: attention branch + uc (concurrent with tail) ----
    cudaStreamWaitEvent(s3, evGE, 0);
    k_gemm16<<<dim3(4, 25), 256, G16_SMEM, s3>>>(
        p_fch, p_fcl, p_kvwh, p_kvwl, ipb + H, p_kv, M, 256, H, 0, nullptr);
    k_attn<<<B, 256, ATTN_SMEM, s3>>>(items, ipw, ipb, opw, opb, w3);
    k_gemm<<<dim3((NC + 63) / 64, 1), 256, 0, s3>>>(p_u, emb + H, p_uc, B, NC, H);
    cudaEventRecord(evUC, s3);

    // ---- s0: tail, then add ----
    cudaStreamWaitEvent(0, evCand, 0);
    k_tail<<<dim3(NCP / 128, B / 8), 256, TAIL_SMEM>>>(items, out);

    cudaStreamWaitEvent(0, evUC, 0);
    k_add<<<(B * NC + 255) / 256, 256>>>(out);
}